// round 14
// baseline (speedup 1.0000x reference)
#include <cuda_runtime.h>
#include <math.h>

#define NE 160000
#define NN 10000
#define N64 (NN*64)
#define NLUT 1024
#define LUT_H   (5.0f/(NLUT-1))
#define LUT_INV ((NLUT-1)/5.0f)

#define S3f  1.7320508075688772f
#define IS3f 0.5773502691896258f
#define S5f  2.2360679774997896f
#define S15f 3.8729833462074170f
#define PIf  3.14159265358979323846f
#define K0C  (0.0625f)
#define K1C  (0.0625f/S3f)
#define K2C  (0.0625f/S5f)
#define K4N  (-0.0625f/S3f)
#define K9N  (0.0625f/S5f)

// ---------------- scratch ----------------
__device__ float d_r[NE];
__device__ float d_Y[NE*8];
__device__ float d_gvec[NE*3];

__device__ float d_lutR0[NLUT*192], d_lutD0[NLUT*192];
__device__ float d_lutR1[NLUT*192], d_lutD1[NLUT*192];
__device__ float2 d_P0[NLUT*192], d_PD0[NLUT*192];
__device__ float2 d_P1[NLUT*192], d_PD1[NLUT*192];

// CSR-ordered edge records: 12 floats = {node|sp<<16, li*192, w, eid, Y[8]}
__device__ float d_erec_r[NE*12];
__device__ float d_erec_s[NE*12];

__device__ int   d_sp[NN];
__device__ float d_hup0v[640];
__device__ float d_sc0v[640];
__device__ float d_h1_0[N64];
__device__ float d_hup1_0[N64];
__device__ float d_hup1_1[3*N64];
__device__ float d_hup1_2[5*N64];
__device__ float d_gagg1[3*N64];
__device__ float d_gh1_0[N64];
__device__ float d_gagg0_0[N64];
__device__ float d_gagg0_1[3*N64];
__device__ float d_gagg0_2[5*N64];
__device__ float d_W01[4096], d_W02[4096];
__device__ float d_e[48];
__device__ int   d_ctr[4];

// CSR
__device__ int d_deg_r[NN], d_deg_s[NN];
__device__ int d_off_r[NN+1], d_off_s[NN+1];
__device__ int d_cur_r[NN], d_cur_s[NN];

__device__ __forceinline__ float siluf(float x){ float s=1.f/(1.f+expf(-x)); return x*s; }
__device__ __forceinline__ float dsiluf(float x){ float s=1.f/(1.f+expf(-x)); return s*(1.f+x*(1.f-s)); }
__device__ __forceinline__ void lut_idx(float r, int& li, float& w){
    float u = fminf(r*LUT_INV, (float)(NLUT-1));
    li = (int)u; if (li > NLUT-2) li = NLUT-2;
    w = u - (float)li;
}
__device__ __forceinline__ float2 lerp2(const float2* __restrict__ P, int idx, float w){
    float4 p = *reinterpret_cast<const float4*>(P+idx);
    return make_float2(fmaf(w,p.y,p.x), fmaf(w,p.w,p.z));
}
__device__ __forceinline__ float warp_sum(float v){
    #pragma unroll
    for (int off=16;off>0;off>>=1) v += __shfl_xor_sync(0xffffffffu, v, off);
    return v;
}

// ---- fused prologue: zeroing + species + precW + prec_sp --------------------
__global__ void k_prep(const float* __restrict__ attrs,
                       const float* __restrict__ w_out0, const float* __restrict__ w_up1,
                       const float* __restrict__ w_emb, const float* __restrict__ w_up0,
                       const float* __restrict__ w_sc0){
    int tid = blockIdx.x*blockDim.x + threadIdx.x;
    int st = gridDim.x*blockDim.x;
    for (int j=tid;j<48;j+=st) d_e[j]=0.f;
    if (tid<4) d_ctr[tid]=0;
    for (int j=tid;j<NN;j+=st){ d_deg_r[j]=0; d_deg_s[j]=0; }
    for (int n=tid;n<NN;n+=st){
        int sp=0;
        for (int q=0;q<10;q++) if (attrs[n*10+q] > 0.5f) sp=q;
        d_sp[n]=sp;
    }
    for (int idx=tid; idx<8192; idx+=st){
        int l = idx>>12, rem = idx&4095, c = rem>>6, d2 = rem&63;
        const float* wo = w_out0 + (l+1)*4096;
        const float* wu = w_up1  + (l+1)*4096;
        float a=0.f;
        for (int d=0;d<64;d++) a = fmaf(wo[c*64+d], wu[d*64+d2], a);
        if (l==0) d_W01[c*64+d2]=a; else d_W02[c*64+d2]=a;
    }
    for (int idx=tid; idx<640; idx+=st){
        int sp = idx>>6, j = idx&63;
        float a=0.f, b=0.f;
        const float* wsc = w_sc0 + sp*4096;
        for (int c=0;c<64;c++){
            float we = w_emb[sp*64+c];
            a = fmaf(we, w_up0[c*64+j], a);
            b = fmaf(we, wsc[c*64+j], b);
        }
        d_hup0v[idx]=a; d_sc0v[idx]=b;
    }
}

__global__ void k_geom_hist(const float* __restrict__ pos, const float* __restrict__ shifts,
                            const int* __restrict__ ei){
    int e = blockIdx.x*blockDim.x + threadIdx.x;
    if (e >= NE) return;
    int s = ei[e], t = ei[NE+e];
    atomicAdd(&d_deg_r[t],1);
    atomicAdd(&d_deg_s[s],1);
    float vx = pos[t*3+0]-pos[s*3+0]+shifts[e*3+0];
    float vy = pos[t*3+1]-pos[s*3+1]+shifts[e*3+1];
    float vz = pos[t*3+2]-pos[s*3+2]+shifts[e*3+2];
    float r  = sqrtf(vx*vx+vy*vy+vz*vz + 1e-12f);
    d_r[e]=r;
    float inv = 1.0f/r;
    float x=vx*inv, y=vy*inv, z=vz*inv;
    d_Y[e*8+0]=S3f*y;  d_Y[e*8+1]=S3f*z;  d_Y[e*8+2]=S3f*x;
    d_Y[e*8+3]=S15f*x*y; d_Y[e*8+4]=S15f*y*z;
    d_Y[e*8+5]=0.5f*S5f*(3.f*z*z-1.f);
    d_Y[e*8+6]=S15f*x*z; d_Y[e*8+7]=0.5f*S15f*(x*x-y*y);
}

// two-block scan (r and s in parallel) + e0 accumulation in block 0 prologue
__global__ void k_scan(const float* __restrict__ aener, const int* __restrict__ batch){
    __shared__ int sh[1024];
    int t = threadIdx.x;
    int w = blockIdx.x;
    if (w==0){
        int n0 = t*10, n1 = min(n0+10, NN);
        if (n0 < NN){
            float acc=0.f; int bcur = batch[n0];
            for (int n=n0;n<n1;n++){
                int b = batch[n];
                if (b != bcur){ atomicAdd(&d_e[bcur], acc); acc=0.f; bcur=b; }
                acc += aener[d_sp[n]];
            }
            atomicAdd(&d_e[bcur], acc);
        }
    }
    int* deg = w? d_deg_s: d_deg_r;
    int* off = w? d_off_s: d_off_r;
    int* cur = w? d_cur_s: d_cur_r;
    int base = t*10, s=0;
    #pragma unroll
    for (int i=0;i<10;i++){ int idx=base+i; if (idx<NN) s+=deg[idx]; }
    sh[t]=s;
    __syncthreads();
    for (int d=1; d<1024; d<<=1){
        int v = (t>=d)? sh[t-d]:0;
        __syncthreads();
        sh[t]+=v;
        __syncthreads();
    }
    int run = sh[t]-s;
    #pragma unroll
    for (int i=0;i<10;i++){ int idx=base+i; if (idx<NN){ off[idx]=run; cur[idx]=run; run+=deg[idx]; } }
    if (t==0) off[NN]=NE;
}

// ------------- LUT build: both MLPs, 8 rows/block, dual-number ---------------
#define MM64x2(DST,SRC) do{ \
    _Pragma("unroll") for(int i=0;i<2;i++) DST[i]=0.f; \
    _Pragma("unroll") for(int k0=0;k0<64;k0+=4){ \
        _Pragma("unroll") for(int i=0;i<2;i++){ \
            float4 a4=*(const float4*)&SRC[r0+i][k0]; \
            DST[i]=fmaf(a4.x,wc[k0],DST[i]); DST[i]=fmaf(a4.y,wc[k0+1],DST[i]); \
            DST[i]=fmaf(a4.z,wc[k0+2],DST[i]); DST[i]=fmaf(a4.w,wc[k0+3],DST[i]); } } \
}while(0)
#define FILLW() _Pragma("unroll") for(int k=0;k<64;k++) wc[k]=sW[k*65+j]

__global__ void __launch_bounds__(256) k_lut_build(
        const float* __restrict__ w1a, const float* __restrict__ w2a,
        const float* __restrict__ w3a, const float* __restrict__ w4a,
        const float* __restrict__ w1b, const float* __restrict__ w2b,
        const float* __restrict__ w3b, const float* __restrict__ w4b){
    int which = blockIdx.y;
    const float* w1 = which? w1b : w1a;
    const float* w2 = which? w2b : w2a;
    const float* w3 = which? w3b : w3a;
    const float* w4 = which? w4b : w4a;
    int w4s = which? 832 : 192;
    int cbs[3]; cbs[0]=0; cbs[1]= which? 256:64; cbs[2]= which? 576:128;
    float kps[3]; kps[0]=K0C; kps[1]= which? K4N:K1C; kps[2]= which? K9N:K2C;
    __shared__ float sV[8][64];
    __shared__ float sT[8][64];
    __shared__ float sW[64*65];
    int tid=threadIdx.x, j=tid&63, r0=(tid>>6)*2;
    int row0=blockIdx.x*8;
    float* LR = which? d_lutR1 : d_lutR0;
    float* LD = which? d_lutD1 : d_lutD0;
    if (tid < 64){
        int rr=tid>>3, q=tid&7;
        float rv = (float)(row0+rr)*LUT_H;
        float rs = fmaxf(rv, 1e-6f);
        float inv = 1.0f/rs;
        float uu = rs*0.2f;
        float u2=uu*uu, u4=u2*u2, u5=u4*uu, u6=u5*uu, u7=u6*uu;
        float fc  = 1.f - 21.f*u5 + 35.f*u6 - 15.f*u7;
        float dfc = (-105.f*u4 + 210.f*u5 - 105.f*u6)*0.2f;
        if (uu >= 1.0f){ fc=0.f; dfc=0.f; }
        float a = (float)(q+1)*(PIf/5.0f);
        float sa=sinf(a*rs), ca=cosf(a*rs);
        float c0 = sqrtf(0.4f);
        sV[rr][q] = c0*sa*inv*fc;
        sT[rr][q] = c0*((a*ca*inv - sa*inv*inv)*fc + sa*inv*dfc);
    }
    __syncthreads();
    float aV[2], aT[2], wc[64];
    #pragma unroll
    for (int i=0;i<2;i++){ aV[i]=0.f; aT[i]=0.f; }
    #pragma unroll
    for (int k=0;k<8;k++){
        float w=w1[k*64+j];
        #pragma unroll
        for (int i=0;i<2;i++){ aV[i]=fmaf(sV[r0+i][k],w,aV[i]); aT[i]=fmaf(sT[r0+i][k],w,aT[i]); }
    }
    __syncthreads();
    #pragma unroll
    for (int i=0;i<2;i++){ float z=aV[i]; sV[r0+i][j]=siluf(z); sT[r0+i][j]=dsiluf(z)*aT[i]; }
    for(int idx=tid; idx<4096; idx+=256){ int a_=idx>>6, b_=idx&63; sW[a_*65+b_]=w2[idx]; }
    __syncthreads();
    FILLW();
    MM64x2(aV, sV);
    MM64x2(aT, sT);
    __syncthreads();
    #pragma unroll
    for (int i=0;i<2;i++){ float z=aV[i]; sV[r0+i][j]=siluf(z); sT[r0+i][j]=dsiluf(z)*aT[i]; }
    for(int idx=tid; idx<4096; idx+=256){ int a_=idx>>6, b_=idx&63; sW[a_*65+b_]=w3[idx]; }
    __syncthreads();
    FILLW();
    MM64x2(aV, sV);
    MM64x2(aT, sT);
    __syncthreads();
    #pragma unroll
    for (int i=0;i<2;i++){ float z=aV[i]; sV[r0+i][j]=siluf(z); sT[r0+i][j]=dsiluf(z)*aT[i]; }
    for (int p=0;p<3;p++){
        for(int idx=tid; idx<4096; idx+=256){ int a_=idx>>6, b_=idx&63; sW[a_*65+b_]=w4[a_*w4s+cbs[p]+b_]; }
        __syncthreads();
        FILLW();
        MM64x2(aV, sV);
        MM64x2(aT, sT);
        float kp = kps[p];
        #pragma unroll
        for (int i=0;i<2;i++){
            LR[(row0+r0+i)*192 + p*64 + j] = kp*aV[i];
            LD[(row0+r0+i)*192 + p*64 + j] = kp*aT[i];
        }
        __syncthreads();
    }
}

// ---- fused: pair-table build + CSR fill (independent works, one launch) -----
#define PAIRB (NLUT*192/256)
__global__ void k_pair_csr(const int* __restrict__ ei){
    int b = blockIdx.x;
    if (b < PAIRB){
        int idx = b*256 + threadIdx.x;
        int li = idx/192;
        int nidx = (li < NLUT-1)? idx+192 : idx;
        float v;
        v = d_lutR0[idx]; d_P0[idx]  = make_float2(v, d_lutR0[nidx]-v);
        v = d_lutD0[idx]; d_PD0[idx] = make_float2(v, d_lutD0[nidx]-v);
        v = d_lutR1[idx]; d_P1[idx]  = make_float2(v, d_lutR1[nidx]-v);
        v = d_lutD1[idx]; d_PD1[idx] = make_float2(v, d_lutD1[nidx]-v);
        return;
    }
    int e = (b-PAIRB)*256 + threadIdx.x;
    if (e >= NE) return;
    int s = ei[e], t = ei[NE+e];
    int sp_s = d_sp[s], sp_t = d_sp[t];
    int li; float w; lut_idx(d_r[e], li, w);
    float y[8];
    #pragma unroll
    for (int i=0;i<8;i++) y[i]=d_Y[e*8+i];
    int p = atomicAdd(&d_cur_r[t],1);
    float* R = d_erec_r + p*12;
    R[0]=__int_as_float(s | (sp_s<<16)); R[1]=__int_as_float(li*192); R[2]=w; R[3]=__int_as_float(e);
    #pragma unroll
    for (int i=0;i<8;i++) R[4+i]=y[i];
    int q = atomicAdd(&d_cur_s[s],1);
    R = d_erec_s + q*12;
    R[0]=__int_as_float(t | (sp_t<<16)); R[1]=__int_as_float(li*192); R[2]=w; R[3]=__int_as_float(e);
    #pragma unroll
    for (int i=0;i<8;i++) R[4+i]=y[i];
}

// ------------------ interaction 0: dynamic queue, 2ch/lane -------------------
#define INT0_EDGE(Rq) { \
    float4 rh=(Rq)[0], ya=(Rq)[1], yb=(Rq)[2]; \
    int v=__float_as_int(rh.x); int spv=v>>16; int base=__float_as_int(rh.y); float w=rh.z; \
    float2 hup=*reinterpret_cast<const float2*>(&sHup[spv*64+c0]); \
    float2 p=lerp2(d_P0, base+c0, w); \
    a0.x=fmaf(hup.x,p.x,a0.x); a0.y=fmaf(hup.y,p.y,a0.y); \
    p=lerp2(d_P0, base+64+c0, w); \
    float m1x=hup.x*p.x, m1y=hup.y*p.y; \
    a1[0].x=fmaf(m1x,ya.x,a1[0].x); a1[0].y=fmaf(m1y,ya.x,a1[0].y); \
    a1[1].x=fmaf(m1x,ya.y,a1[1].x); a1[1].y=fmaf(m1y,ya.y,a1[1].y); \
    a1[2].x=fmaf(m1x,ya.z,a1[2].x); a1[2].y=fmaf(m1y,ya.z,a1[2].y); \
    p=lerp2(d_P0, base+128+c0, w); \
    float m2x=hup.x*p.x, m2y=hup.y*p.y; \
    a2[0].x=fmaf(m2x,ya.w,a2[0].x); a2[0].y=fmaf(m2y,ya.w,a2[0].y); \
    a2[1].x=fmaf(m2x,yb.x,a2[1].x); a2[1].y=fmaf(m2y,yb.x,a2[1].y); \
    a2[2].x=fmaf(m2x,yb.y,a2[2].x); a2[2].y=fmaf(m2y,yb.y,a2[2].y); \
    a2[3].x=fmaf(m2x,yb.z,a2[3].x); a2[3].y=fmaf(m2y,yb.z,a2[3].y); \
    a2[4].x=fmaf(m2x,yb.w,a2[4].x); a2[4].y=fmaf(m2y,yb.w,a2[4].y); \
}

__global__ void __launch_bounds__(256) k_int0(const float* __restrict__ w_out0,
                       const float* __restrict__ w_r0, const float* __restrict__ w_up1,
                       const int* __restrict__ batch){
    int wid=threadIdx.x>>5, l=threadIdx.x&31, c0=l*2;
    __shared__ float sm[8][640];
    __shared__ float sHup[640];
    __shared__ int sBase;
    for (int i=threadIdx.x;i<640;i+=256) sHup[i]=d_hup0v[i];
    float* sA0=sm[wid]; float* sA1=sA0+64; float* sA2=sA1+192; float* sh1=sA2+320;
    for(;;){
        __syncthreads();
        if (threadIdx.x==0) sBase = atomicAdd(&d_ctr[0],1);
        __syncthreads();
        int g = sBase;
        if (g >= NN/8) break;
        int n = g*8 + wid;
        int sp=d_sp[n];
        float2 a0=make_float2(0.f,0.f), a1[3], a2[5];
        #pragma unroll
        for (int i=0;i<3;i++) a1[i]=make_float2(0.f,0.f);
        #pragma unroll
        for (int i=0;i<5;i++) a2[i]=make_float2(0.f,0.f);
        int b0=d_off_r[n], b1=d_off_r[n+1];
        int q=b0;
        for (; q+1<b1; q+=2){
            const float4* R1 = reinterpret_cast<const float4*>(d_erec_r+q*12);
            const float4* R2 = reinterpret_cast<const float4*>(d_erec_r+(q+1)*12);
            INT0_EDGE(R1);
            INT0_EDGE(R2);
        }
        if (q<b1){
            const float4* R1 = reinterpret_cast<const float4*>(d_erec_r+q*12);
            INT0_EDGE(R1);
        }
        sA0[c0]=a0.x; sA0[c0+1]=a0.y;
        #pragma unroll
        for (int i=0;i<3;i++){ sA1[i*64+c0]=a1[i].x; sA1[i*64+c0+1]=a1[i].y; }
        #pragma unroll
        for (int i=0;i<5;i++){ sA2[i*64+c0]=a2[i].x; sA2[i*64+c0+1]=a2[i].y; }
        __syncwarp();
        float2 acc=*reinterpret_cast<const float2*>(&d_sc0v[sp*64+c0]);
        for (int c=0;c<64;c++){
            float va=sA0[c];
            float2 wo=*reinterpret_cast<const float2*>(&w_out0[c*64+c0]);
            acc.x = fmaf(va,wo.x,acc.x);
            acc.y = fmaf(va,wo.y,acc.y);
        }
        *reinterpret_cast<float2*>(&d_h1_0[n*64+c0]) = acc;
        sh1[c0]=acc.x; sh1[c0+1]=acc.y;
        float2 wr=*reinterpret_cast<const float2*>(&w_r0[c0]);
        float ev = warp_sum(acc.x*wr.x + acc.y*wr.y);
        if (l==0) atomicAdd(&d_e[16+batch[n]], ev);
        __syncwarp();
        float2 au=make_float2(0.f,0.f);
        for (int c=0;c<64;c++){
            float vh=sh1[c];
            float2 wu=*reinterpret_cast<const float2*>(&w_up1[c*64+c0]);
            au.x=fmaf(vh,wu.x,au.x); au.y=fmaf(vh,wu.y,au.y);
        }
        *reinterpret_cast<float2*>(&d_hup1_0[n*64+c0]) = au;
        float2 bb[3];
        #pragma unroll
        for (int i=0;i<3;i++) bb[i]=make_float2(0.f,0.f);
        for (int c=0;c<64;c++){
            float2 w2=*reinterpret_cast<const float2*>(&d_W01[c*64+c0]);
            #pragma unroll
            for (int i=0;i<3;i++){
                float v=sA1[i*64+c];
                bb[i].x=fmaf(v,w2.x,bb[i].x); bb[i].y=fmaf(v,w2.y,bb[i].y);
            }
        }
        #pragma unroll
        for (int i=0;i<3;i++) *reinterpret_cast<float2*>(&d_hup1_1[i*N64+n*64+c0]) = bb[i];
        float2 ee[5];
        #pragma unroll
        for (int i=0;i<5;i++) ee[i]=make_float2(0.f,0.f);
        for (int c=0;c<64;c++){
            float2 w2=*reinterpret_cast<const float2*>(&d_W02[c*64+c0]);
            #pragma unroll
            for (int i=0;i<5;i++){
                float v=sA2[i*64+c];
                ee[i].x=fmaf(v,w2.x,ee[i].x); ee[i].y=fmaf(v,w2.y,ee[i].y);
            }
        }
        #pragma unroll
        for (int i=0;i<5;i++) *reinterpret_cast<float2*>(&d_hup1_2[i*N64+n*64+c0]) = ee[i];
    }
}

// ------------------ interaction 1: dynamic queue, 2ch/lane -------------------
#define INT1_EDGE(Rq) { \
    float4 rh=(Rq)[0], ya=(Rq)[1], yb=(Rq)[2]; \
    int s=__float_as_int(rh.x)&0xFFFF; int base=__float_as_int(rh.y); float w=rh.z; \
    float2 h0=*reinterpret_cast<const float2*>(&d_hup1_0[s*64+c0]); \
    float2 p=lerp2(d_P1, base+c0, w); \
    a0.x=fmaf(h0.x,p.x,a0.x); a0.y=fmaf(h0.y,p.y,a0.y); \
    float2 h10=*reinterpret_cast<const float2*>(&d_hup1_1[0*N64+s*64+c0]); \
    float2 h11=*reinterpret_cast<const float2*>(&d_hup1_1[1*N64+s*64+c0]); \
    float2 h12=*reinterpret_cast<const float2*>(&d_hup1_1[2*N64+s*64+c0]); \
    float S1x = ya.x*h10.x + ya.y*h11.x + ya.z*h12.x; \
    float S1y = ya.x*h10.y + ya.y*h11.y + ya.z*h12.y; \
    p=lerp2(d_P1, base+64+c0, w); \
    a1.x=fmaf(S1x,p.x,a1.x); a1.y=fmaf(S1y,p.y,a1.y); \
    float2 h20=*reinterpret_cast<const float2*>(&d_hup1_2[0*N64+s*64+c0]); \
    float2 h21=*reinterpret_cast<const float2*>(&d_hup1_2[1*N64+s*64+c0]); \
    float2 h22=*reinterpret_cast<const float2*>(&d_hup1_2[2*N64+s*64+c0]); \
    float2 h23=*reinterpret_cast<const float2*>(&d_hup1_2[3*N64+s*64+c0]); \
    float2 h24=*reinterpret_cast<const float2*>(&d_hup1_2[4*N64+s*64+c0]); \
    float S2x = ya.w*h20.x + yb.x*h21.x + yb.y*h22.x + yb.z*h23.x + yb.w*h24.x; \
    float S2y = ya.w*h20.y + yb.x*h21.y + yb.y*h22.y + yb.z*h23.y + yb.w*h24.y; \
    p=lerp2(d_P1, base+128+c0, w); \
    a2.x=fmaf(S2x,p.x,a2.x); a2.y=fmaf(S2y,p.y,a2.y); \
}

__global__ void __launch_bounds__(256) k_int1(const float* __restrict__ w_out1,
                       const float* __restrict__ w_sc1, const float* __restrict__ w_m1,
                       const float* __restrict__ w_m2, const float* __restrict__ w_r0,
                       const int* __restrict__ batch){
    int wid=threadIdx.x>>5, l=threadIdx.x&31, c0=l*2;
    __shared__ float sm[8][448];
    __shared__ int sBase;
    float* sA0=sm[wid]; float* sA1=sA0+64; float* sA2=sA1+64; float* sh1=sA2+64;
    float* sh2=sh1+64; float* sg2=sh2+64; float* sdz=sg2+64; float* sv=sdz+16;
    const float* wo0 = w_out1;
    const float* wo4 = w_out1 + 4*4096;
    const float* wo9 = w_out1 + 9*4096;
    for(;;){
        __syncthreads();
        if (threadIdx.x==0) sBase = atomicAdd(&d_ctr[1],1);
        __syncthreads();
        int g = sBase;
        if (g >= NN/8) break;
        int n = g*8 + wid;
        int sp=d_sp[n];
        float2 a0=make_float2(0.f,0.f), a1=make_float2(0.f,0.f), a2=make_float2(0.f,0.f);
        int b0=d_off_r[n], b1=d_off_r[n+1];
        int q=b0;
        for (; q+1<b1; q+=2){
            const float4* R1 = reinterpret_cast<const float4*>(d_erec_r+q*12);
            const float4* R2 = reinterpret_cast<const float4*>(d_erec_r+(q+1)*12);
            INT1_EDGE(R1);
            INT1_EDGE(R2);
        }
        if (q<b1){
            const float4* R1 = reinterpret_cast<const float4*>(d_erec_r+q*12);
            INT1_EDGE(R1);
        }
        sA0[c0]=a0.x; sA0[c0+1]=a0.y;
        sA1[c0]=a1.x; sA1[c0+1]=a1.y;
        sA2[c0]=a2.x; sA2[c0+1]=a2.y;
        float2 h1v=*reinterpret_cast<const float2*>(&d_h1_0[n*64+c0]);
        sh1[c0]=h1v.x; sh1[c0+1]=h1v.y;
        __syncwarp();
        const float* wsc = w_sc1 + sp*4096;
        float2 h2=make_float2(0.f,0.f);
        for (int c=0;c<64;c++){
            float v0=sA0[c], v1=sA1[c], v2=sA2[c], vh=sh1[c];
            float2 wa=*reinterpret_cast<const float2*>(&wo0[c*64+c0]);
            float2 wb=*reinterpret_cast<const float2*>(&wo4[c*64+c0]);
            float2 wcv=*reinterpret_cast<const float2*>(&wo9[c*64+c0]);
            float2 wd=*reinterpret_cast<const float2*>(&wsc[c*64+c0]);
            h2.x = fmaf(v0,wa.x,fmaf(v1,wb.x,fmaf(v2,wcv.x,fmaf(vh,wd.x,h2.x))));
            h2.y = fmaf(v0,wa.y,fmaf(v1,wb.y,fmaf(v2,wcv.y,fmaf(vh,wd.y,h2.y))));
        }
        sh2[c0]=h2.x; sh2[c0+1]=h2.y;
        __syncwarp();
        if (l < 16){
            float z=0.f;
            for (int d=0;d<64;d++) z = fmaf(sh2[d], w_m1[d*16+l], z);
            float s=1.f/(1.f+expf(-z));
            sv[l]  = z*s*w_m2[l];
            sdz[l] = s*(1.f+z*(1.f-s))*w_m2[l];
        }
        __syncwarp();
        if (l==0){
            float t=0.f;
            for (int q2=0;q2<16;q2++) t+=sv[q2];
            atomicAdd(&d_e[32+batch[n]], t);
        }
        float2 gh2=make_float2(0.f,0.f);
        #pragma unroll 4
        for (int q2=0;q2<16;q2++){
            float dz=sdz[q2];
            gh2.x = fmaf(w_m1[c0*16+q2], dz, gh2.x);
            gh2.y = fmaf(w_m1[(c0+1)*16+q2], dz, gh2.y);
        }
        sg2[c0]=gh2.x; sg2[c0+1]=gh2.y;
        __syncwarp();
        float2 wr=*reinterpret_cast<const float2*>(&w_r0[c0]);
        float2 ga0=make_float2(0.f,0.f), ga1=make_float2(0.f,0.f), ga2=make_float2(0.f,0.f);
        float2 gh1=wr;
        for (int d=0;d<64;d+=4){
            float4 g4 = *reinterpret_cast<const float4*>(&sg2[d]);
            float4 wA = *reinterpret_cast<const float4*>(&wo0[c0*64+d]);
            float4 wB = *reinterpret_cast<const float4*>(&wo0[(c0+1)*64+d]);
            ga0.x = fmaf(wA.x,g4.x,fmaf(wA.y,g4.y,fmaf(wA.z,g4.z,fmaf(wA.w,g4.w,ga0.x))));
            ga0.y = fmaf(wB.x,g4.x,fmaf(wB.y,g4.y,fmaf(wB.z,g4.z,fmaf(wB.w,g4.w,ga0.y))));
            wA = *reinterpret_cast<const float4*>(&wo4[c0*64+d]);
            wB = *reinterpret_cast<const float4*>(&wo4[(c0+1)*64+d]);
            ga1.x = fmaf(wA.x,g4.x,fmaf(wA.y,g4.y,fmaf(wA.z,g4.z,fmaf(wA.w,g4.w,ga1.x))));
            ga1.y = fmaf(wB.x,g4.x,fmaf(wB.y,g4.y,fmaf(wB.z,g4.z,fmaf(wB.w,g4.w,ga1.y))));
            wA = *reinterpret_cast<const float4*>(&wo9[c0*64+d]);
            wB = *reinterpret_cast<const float4*>(&wo9[(c0+1)*64+d]);
            ga2.x = fmaf(wA.x,g4.x,fmaf(wA.y,g4.y,fmaf(wA.z,g4.z,fmaf(wA.w,g4.w,ga2.x))));
            ga2.y = fmaf(wB.x,g4.x,fmaf(wB.y,g4.y,fmaf(wB.z,g4.z,fmaf(wB.w,g4.w,ga2.y))));
            wA = *reinterpret_cast<const float4*>(&wsc[c0*64+d]);
            wB = *reinterpret_cast<const float4*>(&wsc[(c0+1)*64+d]);
            gh1.x = fmaf(wA.x,g4.x,fmaf(wA.y,g4.y,fmaf(wA.z,g4.z,fmaf(wA.w,g4.w,gh1.x))));
            gh1.y = fmaf(wB.x,g4.x,fmaf(wB.y,g4.y,fmaf(wB.z,g4.z,fmaf(wB.w,g4.w,gh1.y))));
        }
        *reinterpret_cast<float2*>(&d_gagg1[n*64+c0])=ga0;
        *reinterpret_cast<float2*>(&d_gagg1[N64+n*64+c0])=ga1;
        *reinterpret_cast<float2*>(&d_gagg1[2*N64+n*64+c0])=ga2;
        *reinterpret_cast<float2*>(&d_gh1_0[n*64+c0])=gh1;
    }
}

// --------------- int1 backward: dynamic queue, 2ch/lane ----------------------
#define BWD1_EDGE(Rq) { \
    float4 rh=(Rq)[0], ya=(Rq)[1], yb=(Rq)[2]; \
    int t=__float_as_int(rh.x)&0xFFFF; int base=__float_as_int(rh.y); float w=rh.z; \
    float2 g0=*reinterpret_cast<const float2*>(&d_gagg1[t*64+c0]); \
    float2 g1=*reinterpret_cast<const float2*>(&d_gagg1[N64+t*64+c0]); \
    float2 g2=*reinterpret_cast<const float2*>(&d_gagg1[2*N64+t*64+c0]); \
    float2 p=lerp2(d_P1, base+c0, w); \
    g0a.x=fmaf(p.x,g0.x,g0a.x); g0a.y=fmaf(p.y,g0.y,g0a.y); \
    p=lerp2(d_P1, base+64+c0, w); \
    float a1x=p.x*g1.x, a1y=p.y*g1.y; \
    g1a[0].x=fmaf(a1x,ya.x,g1a[0].x); g1a[0].y=fmaf(a1y,ya.x,g1a[0].y); \
    g1a[1].x=fmaf(a1x,ya.y,g1a[1].x); g1a[1].y=fmaf(a1y,ya.y,g1a[1].y); \
    g1a[2].x=fmaf(a1x,ya.z,g1a[2].x); g1a[2].y=fmaf(a1y,ya.z,g1a[2].y); \
    p=lerp2(d_P1, base+128+c0, w); \
    float a2x=p.x*g2.x, a2y=p.y*g2.y; \
    g2a[0].x=fmaf(a2x,ya.w,g2a[0].x); g2a[0].y=fmaf(a2y,ya.w,g2a[0].y); \
    g2a[1].x=fmaf(a2x,yb.x,g2a[1].x); g2a[1].y=fmaf(a2y,yb.x,g2a[1].y); \
    g2a[2].x=fmaf(a2x,yb.y,g2a[2].x); g2a[2].y=fmaf(a2y,yb.y,g2a[2].y); \
    g2a[3].x=fmaf(a2x,yb.z,g2a[3].x); g2a[3].y=fmaf(a2y,yb.z,g2a[3].y); \
    g2a[4].x=fmaf(a2x,yb.w,g2a[4].x); g2a[4].y=fmaf(a2y,yb.w,g2a[4].y); \
}

__global__ void __launch_bounds__(256) k_int1_bwd(const float* __restrict__ w_up1,
                           const float* __restrict__ w_out0){
    int wid=threadIdx.x>>5, l=threadIdx.x&31, c0=l*2;
    __shared__ float sm[8][640];
    __shared__ int sBase;
    float* sg0=sm[wid]; float* sg1=sg0+64; float* sg2=sg1+192; float* sgh1=sg2+320;
    for(;;){
        __syncthreads();
        if (threadIdx.x==0) sBase = atomicAdd(&d_ctr[2],1);
        __syncthreads();
        int g = sBase;
        if (g >= NN/8) break;
        int n = g*8 + wid;
        float2 g0a=make_float2(0.f,0.f), g1a[3], g2a[5];
        #pragma unroll
        for (int i=0;i<3;i++) g1a[i]=make_float2(0.f,0.f);
        #pragma unroll
        for (int i=0;i<5;i++) g2a[i]=make_float2(0.f,0.f);
        int b0=d_off_s[n], b1=d_off_s[n+1];
        int q=b0;
        for (; q+1<b1; q+=2){
            const float4* R1 = reinterpret_cast<const float4*>(d_erec_s+q*12);
            const float4* R2 = reinterpret_cast<const float4*>(d_erec_s+(q+1)*12);
            BWD1_EDGE(R1);
            BWD1_EDGE(R2);
        }
        if (q<b1){
            const float4* R1 = reinterpret_cast<const float4*>(d_erec_s+q*12);
            BWD1_EDGE(R1);
        }
        sg0[c0]=g0a.x; sg0[c0+1]=g0a.y;
        #pragma unroll
        for (int i=0;i<3;i++){ sg1[i*64+c0]=g1a[i].x; sg1[i*64+c0+1]=g1a[i].y; }
        #pragma unroll
        for (int i=0;i<5;i++){ sg2[i*64+c0]=g2a[i].x; sg2[i*64+c0+1]=g2a[i].y; }
        __syncwarp();
        float2 gh1=*reinterpret_cast<const float2*>(&d_gh1_0[n*64+c0]);
        for (int d=0;d<64;d+=4){
            float4 g4 = *reinterpret_cast<const float4*>(&sg0[d]);
            float4 wA = *reinterpret_cast<const float4*>(&w_up1[c0*64+d]);
            float4 wB = *reinterpret_cast<const float4*>(&w_up1[(c0+1)*64+d]);
            gh1.x = fmaf(wA.x,g4.x,fmaf(wA.y,g4.y,fmaf(wA.z,g4.z,fmaf(wA.w,g4.w,gh1.x))));
            gh1.y = fmaf(wB.x,g4.x,fmaf(wB.y,g4.y,fmaf(wB.z,g4.z,fmaf(wB.w,g4.w,gh1.y))));
        }
        sgh1[c0]=gh1.x; sgh1[c0+1]=gh1.y;
        __syncwarp();
        float2 ga=make_float2(0.f,0.f);
        for (int d=0;d<64;d+=4){
            float4 g4 = *reinterpret_cast<const float4*>(&sgh1[d]);
            float4 wA = *reinterpret_cast<const float4*>(&w_out0[c0*64+d]);
            float4 wB = *reinterpret_cast<const float4*>(&w_out0[(c0+1)*64+d]);
            ga.x = fmaf(wA.x,g4.x,fmaf(wA.y,g4.y,fmaf(wA.z,g4.z,fmaf(wA.w,g4.w,ga.x))));
            ga.y = fmaf(wB.x,g4.x,fmaf(wB.y,g4.y,fmaf(wB.z,g4.z,fmaf(wB.w,g4.w,ga.y))));
        }
        *reinterpret_cast<float2*>(&d_gagg0_0[n*64+c0])=ga;
        float2 bb[3];
        #pragma unroll
        for (int i=0;i<3;i++) bb[i]=make_float2(0.f,0.f);
        for (int d=0;d<64;d+=4){
            float4 wA = *reinterpret_cast<const float4*>(&d_W01[c0*64+d]);
            float4 wB = *reinterpret_cast<const float4*>(&d_W01[(c0+1)*64+d]);
            #pragma unroll
            for (int i=0;i<3;i++){
                float4 g4 = *reinterpret_cast<const float4*>(&sg1[i*64+d]);
                bb[i].x = fmaf(wA.x,g4.x,fmaf(wA.y,g4.y,fmaf(wA.z,g4.z,fmaf(wA.w,g4.w,bb[i].x))));
                bb[i].y = fmaf(wB.x,g4.x,fmaf(wB.y,g4.y,fmaf(wB.z,g4.z,fmaf(wB.w,g4.w,bb[i].y))));
            }
        }
        #pragma unroll
        for (int i=0;i<3;i++) *reinterpret_cast<float2*>(&d_gagg0_1[i*N64+n*64+c0])=bb[i];
        float2 cc[5];
        #pragma unroll
        for (int i=0;i<5;i++) cc[i]=make_float2(0.f,0.f);
        for (int d=0;d<64;d+=4){
            float4 wA = *reinterpret_cast<const float4*>(&d_W02[c0*64+d]);
            float4 wB = *reinterpret_cast<const float4*>(&d_W02[(c0+1)*64+d]);
            #pragma unroll
            for (int i=0;i<5;i++){
                float4 g4 = *reinterpret_cast<const float4*>(&sg2[i*64+d]);
                cc[i].x = fmaf(wA.x,g4.x,fmaf(wA.y,g4.y,fmaf(wA.z,g4.z,fmaf(wA.w,g4.w,cc[i].x))));
                cc[i].y = fmaf(wB.x,g4.x,fmaf(wB.y,g4.y,fmaf(wB.z,g4.z,fmaf(wB.w,g4.w,cc[i].y))));
            }
        }
        #pragma unroll
        for (int i=0;i<5;i++) *reinterpret_cast<float2*>(&d_gagg0_2[i*N64+n*64+c0])=cc[i];
    }
}

// --------- backward edge pass, RECEIVER-ORDERED with hoisted target loads ----
__global__ void __launch_bounds__(256) k_bwd_node(){
    int wid=threadIdx.x>>5, l=threadIdx.x&31, c0=l*2;
    __shared__ float sHup[640];
    __shared__ int sBase;
    for (int i=threadIdx.x;i<640;i+=256) sHup[i]=d_hup0v[i];
    for(;;){
        __syncthreads();
        if (threadIdx.x==0) sBase = atomicAdd(&d_ctr[3],1);
        __syncthreads();
        int g = sBase;
        if (g >= NN/8) break;
        int n = g*8 + wid;
        // hoisted target-side gradients (reused over all incoming edges)
        float2 tg0=*reinterpret_cast<const float2*>(&d_gagg1[n*64+c0]);
        float2 tg1=*reinterpret_cast<const float2*>(&d_gagg1[N64+n*64+c0]);
        float2 tg2=*reinterpret_cast<const float2*>(&d_gagg1[2*N64+n*64+c0]);
        float2 ta0=*reinterpret_cast<const float2*>(&d_gagg0_0[n*64+c0]);
        float2 ta1[3], ta2[5];
        #pragma unroll
        for (int i=0;i<3;i++) ta1[i]=*reinterpret_cast<const float2*>(&d_gagg0_1[i*N64+n*64+c0]);
        #pragma unroll
        for (int i=0;i<5;i++) ta2[i]=*reinterpret_cast<const float2*>(&d_gagg0_2[i*N64+n*64+c0]);
        int b0=d_off_r[n], b1=d_off_r[n+1];
        for (int q=b0;q<b1;q++){
            const float4* Rq = reinterpret_cast<const float4*>(d_erec_r+q*12);
            float4 rh=Rq[0], yA=Rq[1], yB=Rq[2];
            int v=__float_as_int(rh.x); int s=v&0xFFFF, spv=v>>16;
            int base=__float_as_int(rh.y); float w=rh.z;
            int eid=__float_as_int(rh.w);
            float y0=yA.x,y1=yA.y,y2=yA.z,y3=yA.w,y4=yB.x,y5=yB.y,y6=yB.z,y7=yB.w;
            float tY[8]={0,0,0,0,0,0,0,0};
            float gr=0.f;
            // layer 1
            {
                float2 h0=*reinterpret_cast<const float2*>(&d_hup1_0[s*64+c0]);
                float2 h1v[3], h2v[5];
                #pragma unroll
                for (int i=0;i<3;i++) h1v[i]=*reinterpret_cast<const float2*>(&d_hup1_1[i*N64+s*64+c0]);
                #pragma unroll
                for (int i=0;i<5;i++) h2v[i]=*reinterpret_cast<const float2*>(&d_hup1_2[i*N64+s*64+c0]);
                float s1x=y0*h1v[0].x+y1*h1v[1].x+y2*h1v[2].x;
                float s1y=y0*h1v[0].y+y1*h1v[1].y+y2*h1v[2].y;
                float s2x=y3*h2v[0].x+y4*h2v[1].x+y5*h2v[2].x+y6*h2v[3].x+y7*h2v[4].x;
                float s2y=y3*h2v[0].y+y4*h2v[1].y+y5*h2v[2].y+y6*h2v[3].y+y7*h2v[4].y;
                float2 pd=lerp2(d_PD1, base+c0, w);
                gr = fmaf(pd.x, h0.x*tg0.x, gr); gr = fmaf(pd.y, h0.y*tg0.y, gr);
                pd=lerp2(d_PD1, base+64+c0, w);
                gr = fmaf(pd.x, s1x*tg1.x, gr); gr = fmaf(pd.y, s1y*tg1.y, gr);
                pd=lerp2(d_PD1, base+128+c0, w);
                gr = fmaf(pd.x, s2x*tg2.x, gr); gr = fmaf(pd.y, s2y*tg2.y, gr);
                float2 p=lerp2(d_P1, base+64+c0, w);
                float a1x=p.x*tg1.x, a1y=p.y*tg1.y;
                #pragma unroll
                for (int i=0;i<3;i++) tY[i] += a1x*h1v[i].x + a1y*h1v[i].y;
                p=lerp2(d_P1, base+128+c0, w);
                float a2x=p.x*tg2.x, a2y=p.y*tg2.y;
                #pragma unroll
                for (int i=0;i<5;i++) tY[3+i] += a2x*h2v[i].x + a2y*h2v[i].y;
            }
            // layer 0
            {
                float2 hp=*reinterpret_cast<const float2*>(&sHup[spv*64+c0]);
                float s1x=y0*ta1[0].x+y1*ta1[1].x+y2*ta1[2].x;
                float s1y=y0*ta1[0].y+y1*ta1[1].y+y2*ta1[2].y;
                float s2x=y3*ta2[0].x+y4*ta2[1].x+y5*ta2[2].x+y6*ta2[3].x+y7*ta2[4].x;
                float s2y=y3*ta2[0].y+y4*ta2[1].y+y5*ta2[2].y+y6*ta2[3].y+y7*ta2[4].y;
                float2 pd=lerp2(d_PD0, base+c0, w);
                gr = fmaf(pd.x, hp.x*ta0.x, gr); gr = fmaf(pd.y, hp.y*ta0.y, gr);
                pd=lerp2(d_PD0, base+64+c0, w);
                gr = fmaf(pd.x, hp.x*s1x, gr); gr = fmaf(pd.y, hp.y*s1y, gr);
                pd=lerp2(d_PD0, base+128+c0, w);
                gr = fmaf(pd.x, hp.x*s2x, gr); gr = fmaf(pd.y, hp.y*s2y, gr);
                float2 p=lerp2(d_P0, base+64+c0, w);
                float b1x=p.x*hp.x, b1y=p.y*hp.y;
                #pragma unroll
                for (int i=0;i<3;i++) tY[i] += b1x*ta1[i].x + b1y*ta1[i].y;
                p=lerp2(d_P0, base+128+c0, w);
                float b2x=p.x*hp.x, b2y=p.y*hp.y;
                #pragma unroll
                for (int i=0;i<5;i++) tY[3+i] += b2x*ta2[i].x + b2y*ta2[i].y;
            }
            // unit vector from Y1; r from d_r
            float x = y2*IS3f, yv = y0*IS3f, z = y1*IS3f;
            float gux = S3f*tY[2] + S15f*(yv*tY[3] + z*tY[6] + x*tY[7]);
            float guy = S3f*tY[0] + S15f*(x*tY[3] + z*tY[4] - yv*tY[7]);
            float guz = S3f*tY[1] + S15f*(yv*tY[4] + x*tY[6]) + 3.f*S5f*z*tY[5];
            gux = warp_sum(gux); guy = warp_sum(guy); guz = warp_sum(guz);
            gr  = warp_sum(gr);
            if (l==0){
                float r = d_r[eid];
                float inv = 1.0f/r;
                float dot = x*gux + yv*guy + z*guz;
                d_gvec[eid*3+0] = (gux - x*dot)*inv + gr*x;
                d_gvec[eid*3+1] = (guy - yv*dot)*inv + gr*yv;
                d_gvec[eid*3+2] = (guz - z*dot)*inv + gr*z;
            }
        }
    }
}

// ---------------- force gather + finalize (merged) ---------------------------
__global__ void k_force_node(float* __restrict__ out){
    if (blockIdx.x==0 && threadIdx.x<16){
        int g = threadIdx.x;
        float e0=d_e[g], e1=d_e[16+g], e2=d_e[32+g];
        out[g] = e0+e1+e2;
        out[16+g*3+0]=e0; out[16+g*3+1]=e1; out[16+g*3+2]=e2;
    }
    int n = blockIdx.x*4 + (threadIdx.x>>5);
    int lane = threadIdx.x&31;
    float fx=0.f, fy=0.f, fz=0.f;
    int b0=d_off_r[n], b1=d_off_r[n+1];
    for (int q=b0+lane;q<b1;q+=32){
        int e=__float_as_int(d_erec_r[q*12+3]);
        fx-=d_gvec[e*3+0]; fy-=d_gvec[e*3+1]; fz-=d_gvec[e*3+2];
    }
    b0=d_off_s[n]; b1=d_off_s[n+1];
    for (int q=b0+lane;q<b1;q+=32){
        int e=__float_as_int(d_erec_s[q*12+3]);
        fx+=d_gvec[e*3+0]; fy+=d_gvec[e*3+1]; fz+=d_gvec[e*3+2];
    }
    fx=warp_sum(fx); fy=warp_sum(fy); fz=warp_sum(fz);
    if (lane==0){
        float* F = out + 64;
        F[n*3+0]=fx; F[n*3+1]=fy; F[n*3+2]=fz;
    }
}

// ----------------------------------------------------------------------------
extern "C" void kernel_launch(void* const* d_in, const int* in_sizes, int n_in,
                              void* d_out, int out_size){
    const float* pos    = (const float*)d_in[0];
    const float* attrs  = (const float*)d_in[1];
    const float* shifts = (const float*)d_in[2];
    const float* aener  = (const float*)d_in[3];
    const float* w_emb  = (const float*)d_in[4];
    const float* w_up0  = (const float*)d_in[5];
    const float* r0w1   = (const float*)d_in[6];
    const float* r0w2   = (const float*)d_in[7];
    const float* r0w3   = (const float*)d_in[8];
    const float* r0w4   = (const float*)d_in[9];
    const float* w_out0 = (const float*)d_in[10];
    const float* w_sc0  = (const float*)d_in[11];
    const float* w_r0   = (const float*)d_in[12];
    const float* w_up1  = (const float*)d_in[13];
    const float* r1w1   = (const float*)d_in[14];
    const float* r1w2   = (const float*)d_in[15];
    const float* r1w3   = (const float*)d_in[16];
    const float* r1w4   = (const float*)d_in[17];
    const float* w_out1 = (const float*)d_in[18];
    const float* w_sc1  = (const float*)d_in[19];
    const float* w_m1   = (const float*)d_in[20];
    const float* w_m2   = (const float*)d_in[21];
    const int*   ei     = (const int*)d_in[22];
    const int*   batch  = (const int*)d_in[23];
    float* out = (float*)d_out;

    k_prep<<<64,256>>>(attrs, w_out0, w_up1, w_emb, w_up0, w_sc0);
    k_geom_hist<<<625,256>>>(pos, shifts, ei);
    k_scan<<<2,1024>>>(aener, batch);
    k_lut_build<<<dim3(NLUT/8,2),256>>>(r0w1,r0w2,r0w3,r0w4, r1w1,r1w2,r1w3,r1w4);
    k_pair_csr<<<PAIRB+625,256>>>(ei);
    k_int0<<<1184,256>>>(w_out0, w_r0, w_up1, batch);
    k_int1<<<1184,256>>>(w_out1, w_sc1, w_m1, w_m2, w_r0, batch);
    k_int1_bwd<<<1184,256>>>(w_up1, w_out0);
    k_bwd_node<<<1184,256>>>();
    k_force_node<<<NN/4,128>>>(out);
}

// round 15
// speedup vs baseline: 1.0491x; 1.0491x over previous
#include <cuda_runtime.h>
#include <math.h>

#define NE 160000
#define NN 10000
#define N64 (NN*64)
#define NLUT 1024
#define LUT_H   (5.0f/(NLUT-1))
#define LUT_INV ((NLUT-1)/5.0f)

#define S3f  1.7320508075688772f
#define IS3f 0.5773502691896258f
#define S5f  2.2360679774997896f
#define S15f 3.8729833462074170f
#define PIf  3.14159265358979323846f
#define K0C  (0.0625f)
#define K1C  (0.0625f/S3f)
#define K2C  (0.0625f/S5f)
#define K4N  (-0.0625f/S3f)
#define K9N  (0.0625f/S5f)

// ---------------- scratch ----------------
__device__ float d_r[NE];
__device__ float d_Y[NE*8];
__device__ float d_gvec[NE*3];

__device__ float d_lutR0[NLUT*192], d_lutD0[NLUT*192];
__device__ float d_lutR1[NLUT*192], d_lutD1[NLUT*192];
__device__ float2 d_P0[NLUT*192], d_PD0[NLUT*192];
__device__ float2 d_P1[NLUT*192], d_PD1[NLUT*192];

// CSR-ordered edge records: 12 floats = {node|sp<<16, li*192, w, eid, Y[8]}
__device__ float d_erec_r[NE*12];
__device__ float d_erec_s[NE*12];

__device__ int   d_sp[NN];
__device__ float d_hup0v[640];
__device__ float d_sc0v[640];
__device__ float d_h1_0[N64];
__device__ float d_hup1_0[N64];
__device__ float d_hup1_1[3*N64];
__device__ float d_hup1_2[5*N64];
__device__ float d_gagg1[3*N64];
__device__ float d_gh1_0[N64];
__device__ float d_gagg0_0[N64];
__device__ float d_gagg0_1[3*N64];
__device__ float d_gagg0_2[5*N64];
__device__ float d_W01[4096], d_W02[4096];
__device__ float d_e[48];
__device__ int   d_ctr[4];

// CSR
__device__ int d_deg_r[NN], d_deg_s[NN];
__device__ int d_off_r[NN+1], d_off_s[NN+1];
__device__ int d_cur_r[NN], d_cur_s[NN];

__device__ __forceinline__ float siluf(float x){ float s=1.f/(1.f+expf(-x)); return x*s; }
__device__ __forceinline__ float dsiluf(float x){ float s=1.f/(1.f+expf(-x)); return s*(1.f+x*(1.f-s)); }
__device__ __forceinline__ void lut_idx(float r, int& li, float& w){
    float u = fminf(r*LUT_INV, (float)(NLUT-1));
    li = (int)u; if (li > NLUT-2) li = NLUT-2;
    w = u - (float)li;
}
__device__ __forceinline__ float2 lerp2(const float2* __restrict__ P, int idx, float w){
    float4 p = *reinterpret_cast<const float4*>(P+idx);
    return make_float2(fmaf(w,p.y,p.x), fmaf(w,p.w,p.z));
}
__device__ __forceinline__ float warp_sum(float v){
    #pragma unroll
    for (int off=16;off>0;off>>=1) v += __shfl_xor_sync(0xffffffffu, v, off);
    return v;
}

// ---- fused prologue: zeroing + species + precW + prec_sp --------------------
__global__ void k_prep(const float* __restrict__ attrs,
                       const float* __restrict__ w_out0, const float* __restrict__ w_up1,
                       const float* __restrict__ w_emb, const float* __restrict__ w_up0,
                       const float* __restrict__ w_sc0){
    int tid = blockIdx.x*blockDim.x + threadIdx.x;
    int st = gridDim.x*blockDim.x;
    for (int j=tid;j<48;j+=st) d_e[j]=0.f;
    if (tid<4) d_ctr[tid]=0;
    for (int j=tid;j<NN;j+=st){ d_deg_r[j]=0; d_deg_s[j]=0; }
    for (int n=tid;n<NN;n+=st){
        int sp=0;
        for (int q=0;q<10;q++) if (attrs[n*10+q] > 0.5f) sp=q;
        d_sp[n]=sp;
    }
    for (int idx=tid; idx<8192; idx+=st){
        int l = idx>>12, rem = idx&4095, c = rem>>6, d2 = rem&63;
        const float* wo = w_out0 + (l+1)*4096;
        const float* wu = w_up1  + (l+1)*4096;
        float a=0.f;
        for (int d=0;d<64;d++) a = fmaf(wo[c*64+d], wu[d*64+d2], a);
        if (l==0) d_W01[c*64+d2]=a; else d_W02[c*64+d2]=a;
    }
    for (int idx=tid; idx<640; idx+=st){
        int sp = idx>>6, j = idx&63;
        float a=0.f, b=0.f;
        const float* wsc = w_sc0 + sp*4096;
        for (int c=0;c<64;c++){
            float we = w_emb[sp*64+c];
            a = fmaf(we, w_up0[c*64+j], a);
            b = fmaf(we, wsc[c*64+j], b);
        }
        d_hup0v[idx]=a; d_sc0v[idx]=b;
    }
}

__global__ void k_geom_hist(const float* __restrict__ pos, const float* __restrict__ shifts,
                            const int* __restrict__ ei){
    int e = blockIdx.x*blockDim.x + threadIdx.x;
    if (e >= NE) return;
    int s = ei[e], t = ei[NE+e];
    atomicAdd(&d_deg_r[t],1);
    atomicAdd(&d_deg_s[s],1);
    float vx = pos[t*3+0]-pos[s*3+0]+shifts[e*3+0];
    float vy = pos[t*3+1]-pos[s*3+1]+shifts[e*3+1];
    float vz = pos[t*3+2]-pos[s*3+2]+shifts[e*3+2];
    float r  = sqrtf(vx*vx+vy*vy+vz*vz + 1e-12f);
    d_r[e]=r;
    float inv = 1.0f/r;
    float x=vx*inv, y=vy*inv, z=vz*inv;
    d_Y[e*8+0]=S3f*y;  d_Y[e*8+1]=S3f*z;  d_Y[e*8+2]=S3f*x;
    d_Y[e*8+3]=S15f*x*y; d_Y[e*8+4]=S15f*y*z;
    d_Y[e*8+5]=0.5f*S5f*(3.f*z*z-1.f);
    d_Y[e*8+6]=S15f*x*z; d_Y[e*8+7]=0.5f*S15f*(x*x-y*y);
}

// two-block scan (r and s in parallel) + e0 accumulation in block 0 prologue
__global__ void k_scan(const float* __restrict__ aener, const int* __restrict__ batch){
    __shared__ int sh[1024];
    int t = threadIdx.x;
    int w = blockIdx.x;
    if (w==0){
        int n0 = t*10, n1 = min(n0+10, NN);
        if (n0 < NN){
            float acc=0.f; int bcur = batch[n0];
            for (int n=n0;n<n1;n++){
                int b = batch[n];
                if (b != bcur){ atomicAdd(&d_e[bcur], acc); acc=0.f; bcur=b; }
                acc += aener[d_sp[n]];
            }
            atomicAdd(&d_e[bcur], acc);
        }
    }
    int* deg = w? d_deg_s: d_deg_r;
    int* off = w? d_off_s: d_off_r;
    int* cur = w? d_cur_s: d_cur_r;
    int base = t*10, s=0;
    #pragma unroll
    for (int i=0;i<10;i++){ int idx=base+i; if (idx<NN) s+=deg[idx]; }
    sh[t]=s;
    __syncthreads();
    for (int d=1; d<1024; d<<=1){
        int v = (t>=d)? sh[t-d]:0;
        __syncthreads();
        sh[t]+=v;
        __syncthreads();
    }
    int run = sh[t]-s;
    #pragma unroll
    for (int i=0;i<10;i++){ int idx=base+i; if (idx<NN){ off[idx]=run; cur[idx]=run; run+=deg[idx]; } }
    if (t==0) off[NN]=NE;
}

// ------------- LUT build: both MLPs, 8 rows/block, dual-number ---------------
#define MM64x2(DST,SRC) do{ \
    _Pragma("unroll") for(int i=0;i<2;i++) DST[i]=0.f; \
    _Pragma("unroll") for(int k0=0;k0<64;k0+=4){ \
        _Pragma("unroll") for(int i=0;i<2;i++){ \
            float4 a4=*(const float4*)&SRC[r0+i][k0]; \
            DST[i]=fmaf(a4.x,wc[k0],DST[i]); DST[i]=fmaf(a4.y,wc[k0+1],DST[i]); \
            DST[i]=fmaf(a4.z,wc[k0+2],DST[i]); DST[i]=fmaf(a4.w,wc[k0+3],DST[i]); } } \
}while(0)
#define FILLW() _Pragma("unroll") for(int k=0;k<64;k++) wc[k]=sW[k*65+j]

__global__ void __launch_bounds__(256) k_lut_build(
        const float* __restrict__ w1a, const float* __restrict__ w2a,
        const float* __restrict__ w3a, const float* __restrict__ w4a,
        const float* __restrict__ w1b, const float* __restrict__ w2b,
        const float* __restrict__ w3b, const float* __restrict__ w4b){
    int which = blockIdx.y;
    const float* w1 = which? w1b : w1a;
    const float* w2 = which? w2b : w2a;
    const float* w3 = which? w3b : w3a;
    const float* w4 = which? w4b : w4a;
    int w4s = which? 832 : 192;
    int cbs[3]; cbs[0]=0; cbs[1]= which? 256:64; cbs[2]= which? 576:128;
    float kps[3]; kps[0]=K0C; kps[1]= which? K4N:K1C; kps[2]= which? K9N:K2C;
    __shared__ float sV[8][64];
    __shared__ float sT[8][64];
    __shared__ float sW[64*65];
    int tid=threadIdx.x, j=tid&63, r0=(tid>>6)*2;
    int row0=blockIdx.x*8;
    float* LR = which? d_lutR1 : d_lutR0;
    float* LD = which? d_lutD1 : d_lutD0;
    if (tid < 64){
        int rr=tid>>3, q=tid&7;
        float rv = (float)(row0+rr)*LUT_H;
        float rs = fmaxf(rv, 1e-6f);
        float inv = 1.0f/rs;
        float uu = rs*0.2f;
        float u2=uu*uu, u4=u2*u2, u5=u4*uu, u6=u5*uu, u7=u6*uu;
        float fc  = 1.f - 21.f*u5 + 35.f*u6 - 15.f*u7;
        float dfc = (-105.f*u4 + 210.f*u5 - 105.f*u6)*0.2f;
        if (uu >= 1.0f){ fc=0.f; dfc=0.f; }
        float a = (float)(q+1)*(PIf/5.0f);
        float sa=sinf(a*rs), ca=cosf(a*rs);
        float c0 = sqrtf(0.4f);
        sV[rr][q] = c0*sa*inv*fc;
        sT[rr][q] = c0*((a*ca*inv - sa*inv*inv)*fc + sa*inv*dfc);
    }
    __syncthreads();
    float aV[2], aT[2], wc[64];
    #pragma unroll
    for (int i=0;i<2;i++){ aV[i]=0.f; aT[i]=0.f; }
    #pragma unroll
    for (int k=0;k<8;k++){
        float w=w1[k*64+j];
        #pragma unroll
        for (int i=0;i<2;i++){ aV[i]=fmaf(sV[r0+i][k],w,aV[i]); aT[i]=fmaf(sT[r0+i][k],w,aT[i]); }
    }
    __syncthreads();
    #pragma unroll
    for (int i=0;i<2;i++){ float z=aV[i]; sV[r0+i][j]=siluf(z); sT[r0+i][j]=dsiluf(z)*aT[i]; }
    for(int idx=tid; idx<4096; idx+=256){ int a_=idx>>6, b_=idx&63; sW[a_*65+b_]=w2[idx]; }
    __syncthreads();
    FILLW();
    MM64x2(aV, sV);
    MM64x2(aT, sT);
    __syncthreads();
    #pragma unroll
    for (int i=0;i<2;i++){ float z=aV[i]; sV[r0+i][j]=siluf(z); sT[r0+i][j]=dsiluf(z)*aT[i]; }
    for(int idx=tid; idx<4096; idx+=256){ int a_=idx>>6, b_=idx&63; sW[a_*65+b_]=w3[idx]; }
    __syncthreads();
    FILLW();
    MM64x2(aV, sV);
    MM64x2(aT, sT);
    __syncthreads();
    #pragma unroll
    for (int i=0;i<2;i++){ float z=aV[i]; sV[r0+i][j]=siluf(z); sT[r0+i][j]=dsiluf(z)*aT[i]; }
    for (int p=0;p<3;p++){
        for(int idx=tid; idx<4096; idx+=256){ int a_=idx>>6, b_=idx&63; sW[a_*65+b_]=w4[a_*w4s+cbs[p]+b_]; }
        __syncthreads();
        FILLW();
        MM64x2(aV, sV);
        MM64x2(aT, sT);
        float kp = kps[p];
        #pragma unroll
        for (int i=0;i<2;i++){
            LR[(row0+r0+i)*192 + p*64 + j] = kp*aV[i];
            LD[(row0+r0+i)*192 + p*64 + j] = kp*aT[i];
        }
        __syncthreads();
    }
}

// ---- fused: pair-table build + CSR fill (independent works, one launch) -----
#define PAIRB (NLUT*192/256)
__global__ void k_pair_csr(const int* __restrict__ ei){
    int b = blockIdx.x;
    if (b < PAIRB){
        int idx = b*256 + threadIdx.x;
        int li = idx/192;
        int nidx = (li < NLUT-1)? idx+192 : idx;
        float v;
        v = d_lutR0[idx]; d_P0[idx]  = make_float2(v, d_lutR0[nidx]-v);
        v = d_lutD0[idx]; d_PD0[idx] = make_float2(v, d_lutD0[nidx]-v);
        v = d_lutR1[idx]; d_P1[idx]  = make_float2(v, d_lutR1[nidx]-v);
        v = d_lutD1[idx]; d_PD1[idx] = make_float2(v, d_lutD1[nidx]-v);
        return;
    }
    int e = (b-PAIRB)*256 + threadIdx.x;
    if (e >= NE) return;
    int s = ei[e], t = ei[NE+e];
    int sp_s = d_sp[s], sp_t = d_sp[t];
    int li; float w; lut_idx(d_r[e], li, w);
    float y[8];
    #pragma unroll
    for (int i=0;i<8;i++) y[i]=d_Y[e*8+i];
    int p = atomicAdd(&d_cur_r[t],1);
    float* R = d_erec_r + p*12;
    R[0]=__int_as_float(s | (sp_s<<16)); R[1]=__int_as_float(li*192); R[2]=w; R[3]=__int_as_float(e);
    #pragma unroll
    for (int i=0;i<8;i++) R[4+i]=y[i];
    int q = atomicAdd(&d_cur_s[s],1);
    R = d_erec_s + q*12;
    R[0]=__int_as_float(t | (sp_t<<16)); R[1]=__int_as_float(li*192); R[2]=w; R[3]=__int_as_float(e);
    #pragma unroll
    for (int i=0;i<8;i++) R[4+i]=y[i];
}

// ------------------ interaction 0: dynamic queue, 2ch/lane -------------------
#define INT0_EDGE(Rq) { \
    float4 rh=(Rq)[0], ya=(Rq)[1], yb=(Rq)[2]; \
    int v=__float_as_int(rh.x); int spv=v>>16; int base=__float_as_int(rh.y); float w=rh.z; \
    float2 hup=*reinterpret_cast<const float2*>(&sHup[spv*64+c0]); \
    float2 p=lerp2(d_P0, base+c0, w); \
    a0.x=fmaf(hup.x,p.x,a0.x); a0.y=fmaf(hup.y,p.y,a0.y); \
    p=lerp2(d_P0, base+64+c0, w); \
    float m1x=hup.x*p.x, m1y=hup.y*p.y; \
    a1[0].x=fmaf(m1x,ya.x,a1[0].x); a1[0].y=fmaf(m1y,ya.x,a1[0].y); \
    a1[1].x=fmaf(m1x,ya.y,a1[1].x); a1[1].y=fmaf(m1y,ya.y,a1[1].y); \
    a1[2].x=fmaf(m1x,ya.z,a1[2].x); a1[2].y=fmaf(m1y,ya.z,a1[2].y); \
    p=lerp2(d_P0, base+128+c0, w); \
    float m2x=hup.x*p.x, m2y=hup.y*p.y; \
    a2[0].x=fmaf(m2x,ya.w,a2[0].x); a2[0].y=fmaf(m2y,ya.w,a2[0].y); \
    a2[1].x=fmaf(m2x,yb.x,a2[1].x); a2[1].y=fmaf(m2y,yb.x,a2[1].y); \
    a2[2].x=fmaf(m2x,yb.y,a2[2].x); a2[2].y=fmaf(m2y,yb.y,a2[2].y); \
    a2[3].x=fmaf(m2x,yb.z,a2[3].x); a2[3].y=fmaf(m2y,yb.z,a2[3].y); \
    a2[4].x=fmaf(m2x,yb.w,a2[4].x); a2[4].y=fmaf(m2y,yb.w,a2[4].y); \
}

__global__ void __launch_bounds__(256) k_int0(const float* __restrict__ w_out0,
                       const float* __restrict__ w_r0, const float* __restrict__ w_up1,
                       const int* __restrict__ batch){
    int wid=threadIdx.x>>5, l=threadIdx.x&31, c0=l*2;
    __shared__ float sm[8][640];
    __shared__ float sHup[640];
    __shared__ int sBase;
    for (int i=threadIdx.x;i<640;i+=256) sHup[i]=d_hup0v[i];
    float* sA0=sm[wid]; float* sA1=sA0+64; float* sA2=sA1+192; float* sh1=sA2+320;
    for(;;){
        __syncthreads();
        if (threadIdx.x==0) sBase = atomicAdd(&d_ctr[0],1);
        __syncthreads();
        int g = sBase;
        if (g >= NN/8) break;
        int n = g*8 + wid;
        int sp=d_sp[n];
        float2 a0=make_float2(0.f,0.f), a1[3], a2[5];
        #pragma unroll
        for (int i=0;i<3;i++) a1[i]=make_float2(0.f,0.f);
        #pragma unroll
        for (int i=0;i<5;i++) a2[i]=make_float2(0.f,0.f);
        int b0=d_off_r[n], b1=d_off_r[n+1];
        int q=b0;
        for (; q+1<b1; q+=2){
            const float4* R1 = reinterpret_cast<const float4*>(d_erec_r+q*12);
            const float4* R2 = reinterpret_cast<const float4*>(d_erec_r+(q+1)*12);
            INT0_EDGE(R1);
            INT0_EDGE(R2);
        }
        if (q<b1){
            const float4* R1 = reinterpret_cast<const float4*>(d_erec_r+q*12);
            INT0_EDGE(R1);
        }
        sA0[c0]=a0.x; sA0[c0+1]=a0.y;
        #pragma unroll
        for (int i=0;i<3;i++){ sA1[i*64+c0]=a1[i].x; sA1[i*64+c0+1]=a1[i].y; }
        #pragma unroll
        for (int i=0;i<5;i++){ sA2[i*64+c0]=a2[i].x; sA2[i*64+c0+1]=a2[i].y; }
        __syncwarp();
        float2 acc=*reinterpret_cast<const float2*>(&d_sc0v[sp*64+c0]);
        for (int c=0;c<64;c++){
            float va=sA0[c];
            float2 wo=*reinterpret_cast<const float2*>(&w_out0[c*64+c0]);
            acc.x = fmaf(va,wo.x,acc.x);
            acc.y = fmaf(va,wo.y,acc.y);
        }
        *reinterpret_cast<float2*>(&d_h1_0[n*64+c0]) = acc;
        sh1[c0]=acc.x; sh1[c0+1]=acc.y;
        float2 wr=*reinterpret_cast<const float2*>(&w_r0[c0]);
        float ev = warp_sum(acc.x*wr.x + acc.y*wr.y);
        if (l==0) atomicAdd(&d_e[16+batch[n]], ev);
        __syncwarp();
        float2 au=make_float2(0.f,0.f);
        for (int c=0;c<64;c++){
            float vh=sh1[c];
            float2 wu=*reinterpret_cast<const float2*>(&w_up1[c*64+c0]);
            au.x=fmaf(vh,wu.x,au.x); au.y=fmaf(vh,wu.y,au.y);
        }
        *reinterpret_cast<float2*>(&d_hup1_0[n*64+c0]) = au;
        float2 bb[3];
        #pragma unroll
        for (int i=0;i<3;i++) bb[i]=make_float2(0.f,0.f);
        for (int c=0;c<64;c++){
            float2 w2=*reinterpret_cast<const float2*>(&d_W01[c*64+c0]);
            #pragma unroll
            for (int i=0;i<3;i++){
                float v=sA1[i*64+c];
                bb[i].x=fmaf(v,w2.x,bb[i].x); bb[i].y=fmaf(v,w2.y,bb[i].y);
            }
        }
        #pragma unroll
        for (int i=0;i<3;i++) *reinterpret_cast<float2*>(&d_hup1_1[i*N64+n*64+c0]) = bb[i];
        float2 ee[5];
        #pragma unroll
        for (int i=0;i<5;i++) ee[i]=make_float2(0.f,0.f);
        for (int c=0;c<64;c++){
            float2 w2=*reinterpret_cast<const float2*>(&d_W02[c*64+c0]);
            #pragma unroll
            for (int i=0;i<5;i++){
                float v=sA2[i*64+c];
                ee[i].x=fmaf(v,w2.x,ee[i].x); ee[i].y=fmaf(v,w2.y,ee[i].y);
            }
        }
        #pragma unroll
        for (int i=0;i<5;i++) *reinterpret_cast<float2*>(&d_hup1_2[i*N64+n*64+c0]) = ee[i];
    }
}

// ------------------ interaction 1: dynamic queue, 2ch/lane -------------------
#define INT1_EDGE(Rq) { \
    float4 rh=(Rq)[0], ya=(Rq)[1], yb=(Rq)[2]; \
    int s=__float_as_int(rh.x)&0xFFFF; int base=__float_as_int(rh.y); float w=rh.z; \
    float2 h0=*reinterpret_cast<const float2*>(&d_hup1_0[s*64+c0]); \
    float2 p=lerp2(d_P1, base+c0, w); \
    a0.x=fmaf(h0.x,p.x,a0.x); a0.y=fmaf(h0.y,p.y,a0.y); \
    float2 h10=*reinterpret_cast<const float2*>(&d_hup1_1[0*N64+s*64+c0]); \
    float2 h11=*reinterpret_cast<const float2*>(&d_hup1_1[1*N64+s*64+c0]); \
    float2 h12=*reinterpret_cast<const float2*>(&d_hup1_1[2*N64+s*64+c0]); \
    float S1x = ya.x*h10.x + ya.y*h11.x + ya.z*h12.x; \
    float S1y = ya.x*h10.y + ya.y*h11.y + ya.z*h12.y; \
    p=lerp2(d_P1, base+64+c0, w); \
    a1.x=fmaf(S1x,p.x,a1.x); a1.y=fmaf(S1y,p.y,a1.y); \
    float2 h20=*reinterpret_cast<const float2*>(&d_hup1_2[0*N64+s*64+c0]); \
    float2 h21=*reinterpret_cast<const float2*>(&d_hup1_2[1*N64+s*64+c0]); \
    float2 h22=*reinterpret_cast<const float2*>(&d_hup1_2[2*N64+s*64+c0]); \
    float2 h23=*reinterpret_cast<const float2*>(&d_hup1_2[3*N64+s*64+c0]); \
    float2 h24=*reinterpret_cast<const float2*>(&d_hup1_2[4*N64+s*64+c0]); \
    float S2x = ya.w*h20.x + yb.x*h21.x + yb.y*h22.x + yb.z*h23.x + yb.w*h24.x; \
    float S2y = ya.w*h20.y + yb.x*h21.y + yb.y*h22.y + yb.z*h23.y + yb.w*h24.y; \
    p=lerp2(d_P1, base+128+c0, w); \
    a2.x=fmaf(S2x,p.x,a2.x); a2.y=fmaf(S2y,p.y,a2.y); \
}

__global__ void __launch_bounds__(256) k_int1(const float* __restrict__ w_out1,
                       const float* __restrict__ w_sc1, const float* __restrict__ w_m1,
                       const float* __restrict__ w_m2, const float* __restrict__ w_r0,
                       const int* __restrict__ batch){
    int wid=threadIdx.x>>5, l=threadIdx.x&31, c0=l*2;
    __shared__ float sm[8][448];
    __shared__ int sBase;
    float* sA0=sm[wid]; float* sA1=sA0+64; float* sA2=sA1+64; float* sh1=sA2+64;
    float* sh2=sh1+64; float* sg2=sh2+64; float* sdz=sg2+64; float* sv=sdz+16;
    const float* wo0 = w_out1;
    const float* wo4 = w_out1 + 4*4096;
    const float* wo9 = w_out1 + 9*4096;
    for(;;){
        __syncthreads();
        if (threadIdx.x==0) sBase = atomicAdd(&d_ctr[1],1);
        __syncthreads();
        int g = sBase;
        if (g >= NN/8) break;
        int n = g*8 + wid;
        int sp=d_sp[n];
        float2 a0=make_float2(0.f,0.f), a1=make_float2(0.f,0.f), a2=make_float2(0.f,0.f);
        int b0=d_off_r[n], b1=d_off_r[n+1];
        int q=b0;
        for (; q+1<b1; q+=2){
            const float4* R1 = reinterpret_cast<const float4*>(d_erec_r+q*12);
            const float4* R2 = reinterpret_cast<const float4*>(d_erec_r+(q+1)*12);
            INT1_EDGE(R1);
            INT1_EDGE(R2);
        }
        if (q<b1){
            const float4* R1 = reinterpret_cast<const float4*>(d_erec_r+q*12);
            INT1_EDGE(R1);
        }
        sA0[c0]=a0.x; sA0[c0+1]=a0.y;
        sA1[c0]=a1.x; sA1[c0+1]=a1.y;
        sA2[c0]=a2.x; sA2[c0+1]=a2.y;
        float2 h1v=*reinterpret_cast<const float2*>(&d_h1_0[n*64+c0]);
        sh1[c0]=h1v.x; sh1[c0+1]=h1v.y;
        __syncwarp();
        const float* wsc = w_sc1 + sp*4096;
        float2 h2=make_float2(0.f,0.f);
        for (int c=0;c<64;c++){
            float v0=sA0[c], v1=sA1[c], v2=sA2[c], vh=sh1[c];
            float2 wa=*reinterpret_cast<const float2*>(&wo0[c*64+c0]);
            float2 wb=*reinterpret_cast<const float2*>(&wo4[c*64+c0]);
            float2 wcv=*reinterpret_cast<const float2*>(&wo9[c*64+c0]);
            float2 wd=*reinterpret_cast<const float2*>(&wsc[c*64+c0]);
            h2.x = fmaf(v0,wa.x,fmaf(v1,wb.x,fmaf(v2,wcv.x,fmaf(vh,wd.x,h2.x))));
            h2.y = fmaf(v0,wa.y,fmaf(v1,wb.y,fmaf(v2,wcv.y,fmaf(vh,wd.y,h2.y))));
        }
        sh2[c0]=h2.x; sh2[c0+1]=h2.y;
        __syncwarp();
        if (l < 16){
            float z=0.f;
            for (int d=0;d<64;d++) z = fmaf(sh2[d], w_m1[d*16+l], z);
            float s=1.f/(1.f+expf(-z));
            sv[l]  = z*s*w_m2[l];
            sdz[l] = s*(1.f+z*(1.f-s))*w_m2[l];
        }
        __syncwarp();
        if (l==0){
            float t=0.f;
            for (int q2=0;q2<16;q2++) t+=sv[q2];
            atomicAdd(&d_e[32+batch[n]], t);
        }
        float2 gh2=make_float2(0.f,0.f);
        #pragma unroll 4
        for (int q2=0;q2<16;q2++){
            float dz=sdz[q2];
            gh2.x = fmaf(w_m1[c0*16+q2], dz, gh2.x);
            gh2.y = fmaf(w_m1[(c0+1)*16+q2], dz, gh2.y);
        }
        sg2[c0]=gh2.x; sg2[c0+1]=gh2.y;
        __syncwarp();
        float2 wr=*reinterpret_cast<const float2*>(&w_r0[c0]);
        float2 ga0=make_float2(0.f,0.f), ga1=make_float2(0.f,0.f), ga2=make_float2(0.f,0.f);
        float2 gh1=wr;
        for (int d=0;d<64;d+=4){
            float4 g4 = *reinterpret_cast<const float4*>(&sg2[d]);
            float4 wA = *reinterpret_cast<const float4*>(&wo0[c0*64+d]);
            float4 wB = *reinterpret_cast<const float4*>(&wo0[(c0+1)*64+d]);
            ga0.x = fmaf(wA.x,g4.x,fmaf(wA.y,g4.y,fmaf(wA.z,g4.z,fmaf(wA.w,g4.w,ga0.x))));
            ga0.y = fmaf(wB.x,g4.x,fmaf(wB.y,g4.y,fmaf(wB.z,g4.z,fmaf(wB.w,g4.w,ga0.y))));
            wA = *reinterpret_cast<const float4*>(&wo4[c0*64+d]);
            wB = *reinterpret_cast<const float4*>(&wo4[(c0+1)*64+d]);
            ga1.x = fmaf(wA.x,g4.x,fmaf(wA.y,g4.y,fmaf(wA.z,g4.z,fmaf(wA.w,g4.w,ga1.x))));
            ga1.y = fmaf(wB.x,g4.x,fmaf(wB.y,g4.y,fmaf(wB.z,g4.z,fmaf(wB.w,g4.w,ga1.y))));
            wA = *reinterpret_cast<const float4*>(&wo9[c0*64+d]);
            wB = *reinterpret_cast<const float4*>(&wo9[(c0+1)*64+d]);
            ga2.x = fmaf(wA.x,g4.x,fmaf(wA.y,g4.y,fmaf(wA.z,g4.z,fmaf(wA.w,g4.w,ga2.x))));
            ga2.y = fmaf(wB.x,g4.x,fmaf(wB.y,g4.y,fmaf(wB.z,g4.z,fmaf(wB.w,g4.w,ga2.y))));
            wA = *reinterpret_cast<const float4*>(&wsc[c0*64+d]);
            wB = *reinterpret_cast<const float4*>(&wsc[(c0+1)*64+d]);
            gh1.x = fmaf(wA.x,g4.x,fmaf(wA.y,g4.y,fmaf(wA.z,g4.z,fmaf(wA.w,g4.w,gh1.x))));
            gh1.y = fmaf(wB.x,g4.x,fmaf(wB.y,g4.y,fmaf(wB.z,g4.z,fmaf(wB.w,g4.w,gh1.y))));
        }
        *reinterpret_cast<float2*>(&d_gagg1[n*64+c0])=ga0;
        *reinterpret_cast<float2*>(&d_gagg1[N64+n*64+c0])=ga1;
        *reinterpret_cast<float2*>(&d_gagg1[2*N64+n*64+c0])=ga2;
        *reinterpret_cast<float2*>(&d_gh1_0[n*64+c0])=gh1;
    }
}

// --------------- int1 backward: dynamic queue, 2ch/lane ----------------------
#define BWD1_EDGE(Rq) { \
    float4 rh=(Rq)[0], ya=(Rq)[1], yb=(Rq)[2]; \
    int t=__float_as_int(rh.x)&0xFFFF; int base=__float_as_int(rh.y); float w=rh.z; \
    float2 g0=*reinterpret_cast<const float2*>(&d_gagg1[t*64+c0]); \
    float2 g1=*reinterpret_cast<const float2*>(&d_gagg1[N64+t*64+c0]); \
    float2 g2=*reinterpret_cast<const float2*>(&d_gagg1[2*N64+t*64+c0]); \
    float2 p=lerp2(d_P1, base+c0, w); \
    g0a.x=fmaf(p.x,g0.x,g0a.x); g0a.y=fmaf(p.y,g0.y,g0a.y); \
    p=lerp2(d_P1, base+64+c0, w); \
    float a1x=p.x*g1.x, a1y=p.y*g1.y; \
    g1a[0].x=fmaf(a1x,ya.x,g1a[0].x); g1a[0].y=fmaf(a1y,ya.x,g1a[0].y); \
    g1a[1].x=fmaf(a1x,ya.y,g1a[1].x); g1a[1].y=fmaf(a1y,ya.y,g1a[1].y); \
    g1a[2].x=fmaf(a1x,ya.z,g1a[2].x); g1a[2].y=fmaf(a1y,ya.z,g1a[2].y); \
    p=lerp2(d_P1, base+128+c0, w); \
    float a2x=p.x*g2.x, a2y=p.y*g2.y; \
    g2a[0].x=fmaf(a2x,ya.w,g2a[0].x); g2a[0].y=fmaf(a2y,ya.w,g2a[0].y); \
    g2a[1].x=fmaf(a2x,yb.x,g2a[1].x); g2a[1].y=fmaf(a2y,yb.x,g2a[1].y); \
    g2a[2].x=fmaf(a2x,yb.y,g2a[2].x); g2a[2].y=fmaf(a2y,yb.y,g2a[2].y); \
    g2a[3].x=fmaf(a2x,yb.z,g2a[3].x); g2a[3].y=fmaf(a2y,yb.z,g2a[3].y); \
    g2a[4].x=fmaf(a2x,yb.w,g2a[4].x); g2a[4].y=fmaf(a2y,yb.w,g2a[4].y); \
}

__global__ void __launch_bounds__(256) k_int1_bwd(const float* __restrict__ w_up1,
                           const float* __restrict__ w_out0){
    int wid=threadIdx.x>>5, l=threadIdx.x&31, c0=l*2;
    __shared__ float sm[8][640];
    __shared__ int sBase;
    float* sg0=sm[wid]; float* sg1=sg0+64; float* sg2=sg1+192; float* sgh1=sg2+320;
    for(;;){
        __syncthreads();
        if (threadIdx.x==0) sBase = atomicAdd(&d_ctr[2],1);
        __syncthreads();
        int g = sBase;
        if (g >= NN/8) break;
        int n = g*8 + wid;
        float2 g0a=make_float2(0.f,0.f), g1a[3], g2a[5];
        #pragma unroll
        for (int i=0;i<3;i++) g1a[i]=make_float2(0.f,0.f);
        #pragma unroll
        for (int i=0;i<5;i++) g2a[i]=make_float2(0.f,0.f);
        int b0=d_off_s[n], b1=d_off_s[n+1];
        int q=b0;
        for (; q+1<b1; q+=2){
            const float4* R1 = reinterpret_cast<const float4*>(d_erec_s+q*12);
            const float4* R2 = reinterpret_cast<const float4*>(d_erec_s+(q+1)*12);
            BWD1_EDGE(R1);
            BWD1_EDGE(R2);
        }
        if (q<b1){
            const float4* R1 = reinterpret_cast<const float4*>(d_erec_s+q*12);
            BWD1_EDGE(R1);
        }
        sg0[c0]=g0a.x; sg0[c0+1]=g0a.y;
        #pragma unroll
        for (int i=0;i<3;i++){ sg1[i*64+c0]=g1a[i].x; sg1[i*64+c0+1]=g1a[i].y; }
        #pragma unroll
        for (int i=0;i<5;i++){ sg2[i*64+c0]=g2a[i].x; sg2[i*64+c0+1]=g2a[i].y; }
        __syncwarp();
        float2 gh1=*reinterpret_cast<const float2*>(&d_gh1_0[n*64+c0]);
        for (int d=0;d<64;d+=4){
            float4 g4 = *reinterpret_cast<const float4*>(&sg0[d]);
            float4 wA = *reinterpret_cast<const float4*>(&w_up1[c0*64+d]);
            float4 wB = *reinterpret_cast<const float4*>(&w_up1[(c0+1)*64+d]);
            gh1.x = fmaf(wA.x,g4.x,fmaf(wA.y,g4.y,fmaf(wA.z,g4.z,fmaf(wA.w,g4.w,gh1.x))));
            gh1.y = fmaf(wB.x,g4.x,fmaf(wB.y,g4.y,fmaf(wB.z,g4.z,fmaf(wB.w,g4.w,gh1.y))));
        }
        sgh1[c0]=gh1.x; sgh1[c0+1]=gh1.y;
        __syncwarp();
        float2 ga=make_float2(0.f,0.f);
        for (int d=0;d<64;d+=4){
            float4 g4 = *reinterpret_cast<const float4*>(&sgh1[d]);
            float4 wA = *reinterpret_cast<const float4*>(&w_out0[c0*64+d]);
            float4 wB = *reinterpret_cast<const float4*>(&w_out0[(c0+1)*64+d]);
            ga.x = fmaf(wA.x,g4.x,fmaf(wA.y,g4.y,fmaf(wA.z,g4.z,fmaf(wA.w,g4.w,ga.x))));
            ga.y = fmaf(wB.x,g4.x,fmaf(wB.y,g4.y,fmaf(wB.z,g4.z,fmaf(wB.w,g4.w,ga.y))));
        }
        *reinterpret_cast<float2*>(&d_gagg0_0[n*64+c0])=ga;
        float2 bb[3];
        #pragma unroll
        for (int i=0;i<3;i++) bb[i]=make_float2(0.f,0.f);
        for (int d=0;d<64;d+=4){
            float4 wA = *reinterpret_cast<const float4*>(&d_W01[c0*64+d]);
            float4 wB = *reinterpret_cast<const float4*>(&d_W01[(c0+1)*64+d]);
            #pragma unroll
            for (int i=0;i<3;i++){
                float4 g4 = *reinterpret_cast<const float4*>(&sg1[i*64+d]);
                bb[i].x = fmaf(wA.x,g4.x,fmaf(wA.y,g4.y,fmaf(wA.z,g4.z,fmaf(wA.w,g4.w,bb[i].x))));
                bb[i].y = fmaf(wB.x,g4.x,fmaf(wB.y,g4.y,fmaf(wB.z,g4.z,fmaf(wB.w,g4.w,bb[i].y))));
            }
        }
        #pragma unroll
        for (int i=0;i<3;i++) *reinterpret_cast<float2*>(&d_gagg0_1[i*N64+n*64+c0])=bb[i];
        float2 cc[5];
        #pragma unroll
        for (int i=0;i<5;i++) cc[i]=make_float2(0.f,0.f);
        for (int d=0;d<64;d+=4){
            float4 wA = *reinterpret_cast<const float4*>(&d_W02[c0*64+d]);
            float4 wB = *reinterpret_cast<const float4*>(&d_W02[(c0+1)*64+d]);
            #pragma unroll
            for (int i=0;i<5;i++){
                float4 g4 = *reinterpret_cast<const float4*>(&sg2[i*64+d]);
                cc[i].x = fmaf(wA.x,g4.x,fmaf(wA.y,g4.y,fmaf(wA.z,g4.z,fmaf(wA.w,g4.w,cc[i].x))));
                cc[i].y = fmaf(wB.x,g4.x,fmaf(wB.y,g4.y,fmaf(wB.z,g4.z,fmaf(wB.w,g4.w,cc[i].y))));
            }
        }
        #pragma unroll
        for (int i=0;i<5;i++) *reinterpret_cast<float2*>(&d_gagg0_2[i*N64+n*64+c0])=cc[i];
    }
}

// --------- FUSED backward edge pass (warp-per-edge): both layers -> gvec -----
__global__ void k_bwd_edge(const int* __restrict__ ei){
    int gtid = blockIdx.x*blockDim.x + threadIdx.x;
    int e = gtid>>5, lane = gtid&31, c0=lane*2;
    int s = ei[e], t = ei[NE+e];
    int sp_s = d_sp[s];
    float r = d_r[e];
    int li; float w; lut_idx(r, li, w);
    int base = li*192;
    float4 ya = *reinterpret_cast<const float4*>(&d_Y[e*8]);
    float4 yb = *reinterpret_cast<const float4*>(&d_Y[e*8+4]);
    float y[8]={ya.x,ya.y,ya.z,ya.w,yb.x,yb.y,yb.z,yb.w};
    float tY[8]={0,0,0,0,0,0,0,0};
    float gr=0.f;
    // ---- layer 1 backward ----
    {
        float2 g0=*reinterpret_cast<const float2*>(&d_gagg1[t*64+c0]);
        float2 g1=*reinterpret_cast<const float2*>(&d_gagg1[N64+t*64+c0]);
        float2 g2=*reinterpret_cast<const float2*>(&d_gagg1[2*N64+t*64+c0]);
        float2 h0=*reinterpret_cast<const float2*>(&d_hup1_0[s*64+c0]);
        float2 h1v[3], h2v[5];
        #pragma unroll
        for (int i=0;i<3;i++) h1v[i]=*reinterpret_cast<const float2*>(&d_hup1_1[i*N64+s*64+c0]);
        #pragma unroll
        for (int i=0;i<5;i++) h2v[i]=*reinterpret_cast<const float2*>(&d_hup1_2[i*N64+s*64+c0]);
        float s1x=y[0]*h1v[0].x+y[1]*h1v[1].x+y[2]*h1v[2].x;
        float s1y=y[0]*h1v[0].y+y[1]*h1v[1].y+y[2]*h1v[2].y;
        float s2x=y[3]*h2v[0].x+y[4]*h2v[1].x+y[5]*h2v[2].x+y[6]*h2v[3].x+y[7]*h2v[4].x;
        float s2y=y[3]*h2v[0].y+y[4]*h2v[1].y+y[5]*h2v[2].y+y[6]*h2v[3].y+y[7]*h2v[4].y;
        float2 pd=lerp2(d_PD1, base+c0, w);
        gr = fmaf(pd.x, h0.x*g0.x, gr); gr = fmaf(pd.y, h0.y*g0.y, gr);
        pd=lerp2(d_PD1, base+64+c0, w);
        gr = fmaf(pd.x, s1x*g1.x, gr); gr = fmaf(pd.y, s1y*g1.y, gr);
        pd=lerp2(d_PD1, base+128+c0, w);
        gr = fmaf(pd.x, s2x*g2.x, gr); gr = fmaf(pd.y, s2y*g2.y, gr);
        float2 p=lerp2(d_P1, base+64+c0, w);
        float a1x=p.x*g1.x, a1y=p.y*g1.y;
        #pragma unroll
        for (int i=0;i<3;i++) tY[i] += a1x*h1v[i].x + a1y*h1v[i].y;
        p=lerp2(d_P1, base+128+c0, w);
        float a2x=p.x*g2.x, a2y=p.y*g2.y;
        #pragma unroll
        for (int i=0;i<5;i++) tY[3+i] += a2x*h2v[i].x + a2y*h2v[i].y;
    }
    // ---- layer 0 backward ----
    {
        float2 hp=*reinterpret_cast<const float2*>(&d_hup0v[sp_s*64+c0]);
        float2 ga0=*reinterpret_cast<const float2*>(&d_gagg0_0[t*64+c0]);
        float2 ga1[3], ga2[5];
        #pragma unroll
        for (int i=0;i<3;i++) ga1[i]=*reinterpret_cast<const float2*>(&d_gagg0_1[i*N64+t*64+c0]);
        #pragma unroll
        for (int i=0;i<5;i++) ga2[i]=*reinterpret_cast<const float2*>(&d_gagg0_2[i*N64+t*64+c0]);
        float s1x=y[0]*ga1[0].x+y[1]*ga1[1].x+y[2]*ga1[2].x;
        float s1y=y[0]*ga1[0].y+y[1]*ga1[1].y+y[2]*ga1[2].y;
        float s2x=y[3]*ga2[0].x+y[4]*ga2[1].x+y[5]*ga2[2].x+y[6]*ga2[3].x+y[7]*ga2[4].x;
        float s2y=y[3]*ga2[0].y+y[4]*ga2[1].y+y[5]*ga2[2].y+y[6]*ga2[3].y+y[7]*ga2[4].y;
        float2 pd=lerp2(d_PD0, base+c0, w);
        gr = fmaf(pd.x, hp.x*ga0.x, gr); gr = fmaf(pd.y, hp.y*ga0.y, gr);
        pd=lerp2(d_PD0, base+64+c0, w);
        gr = fmaf(pd.x, hp.x*s1x, gr); gr = fmaf(pd.y, hp.y*s1y, gr);
        pd=lerp2(d_PD0, base+128+c0, w);
        gr = fmaf(pd.x, hp.x*s2x, gr); gr = fmaf(pd.y, hp.y*s2y, gr);
        float2 p=lerp2(d_P0, base+64+c0, w);
        float b1x=p.x*hp.x, b1y=p.y*hp.y;
        #pragma unroll
        for (int i=0;i<3;i++) tY[i] += b1x*ga1[i].x + b1y*ga1[i].y;
        p=lerp2(d_P0, base+128+c0, w);
        float b2x=p.x*hp.x, b2y=p.y*hp.y;
        #pragma unroll
        for (int i=0;i<5;i++) tY[3+i] += b2x*ga2[i].x + b2y*ga2[i].y;
    }
    // unit vector from Y1 (x=Y2/√3, y=Y0/√3, z=Y1/√3); fold tY into 3 partials
    float x = y[2]*IS3f, yv = y[0]*IS3f, z = y[1]*IS3f;
    float gux = S3f*tY[2] + S15f*(yv*tY[3] + z*tY[6] + x*tY[7]);
    float guy = S3f*tY[0] + S15f*(x*tY[3] + z*tY[4] - yv*tY[7]);
    float guz = S3f*tY[1] + S15f*(yv*tY[4] + x*tY[6]) + 3.f*S5f*z*tY[5];
    gux = warp_sum(gux); guy = warp_sum(guy); guz = warp_sum(guz);
    gr  = warp_sum(gr);
    if (lane==0){
        float inv = 1.0f/r;
        float dot = x*gux + yv*guy + z*guz;
        d_gvec[e*3+0] = (gux - x*dot)*inv + gr*x;
        d_gvec[e*3+1] = (guy - yv*dot)*inv + gr*yv;
        d_gvec[e*3+2] = (guz - z*dot)*inv + gr*z;
    }
}

// ---------------- force gather + finalize (merged) ---------------------------
__global__ void k_force_node(float* __restrict__ out){
    if (blockIdx.x==0 && threadIdx.x<16){
        int g = threadIdx.x;
        float e0=d_e[g], e1=d_e[16+g], e2=d_e[32+g];
        out[g] = e0+e1+e2;
        out[16+g*3+0]=e0; out[16+g*3+1]=e1; out[16+g*3+2]=e2;
    }
    int n = blockIdx.x*4 + (threadIdx.x>>5);
    int lane = threadIdx.x&31;
    float fx=0.f, fy=0.f, fz=0.f;
    int b0=d_off_r[n], b1=d_off_r[n+1];
    for (int q=b0+lane;q<b1;q+=32){
        int e=__float_as_int(d_erec_r[q*12+3]);
        fx-=d_gvec[e*3+0]; fy-=d_gvec[e*3+1]; fz-=d_gvec[e*3+2];
    }
    b0=d_off_s[n]; b1=d_off_s[n+1];
    for (int q=b0+lane;q<b1;q+=32){
        int e=__float_as_int(d_erec_s[q*12+3]);
        fx+=d_gvec[e*3+0]; fy+=d_gvec[e*3+1]; fz+=d_gvec[e*3+2];
    }
    fx=warp_sum(fx); fy=warp_sum(fy); fz=warp_sum(fz);
    if (lane==0){
        float* F = out + 64;
        F[n*3+0]=fx; F[n*3+1]=fy; F[n*3+2]=fz;
    }
}

// ----------------------------------------------------------------------------
extern "C" void kernel_launch(void* const* d_in, const int* in_sizes, int n_in,
                              void* d_out, int out_size){
    const float* pos    = (const float*)d_in[0];
    const float* attrs  = (const float*)d_in[1];
    const float* shifts = (const float*)d_in[2];
    const float* aener  = (const float*)d_in[3];
    const float* w_emb  = (const float*)d_in[4];
    const float* w_up0  = (const float*)d_in[5];
    const float* r0w1   = (const float*)d_in[6];
    const float* r0w2   = (const float*)d_in[7];
    const float* r0w3   = (const float*)d_in[8];
    const float* r0w4   = (const float*)d_in[9];
    const float* w_out0 = (const float*)d_in[10];
    const float* w_sc0  = (const float*)d_in[11];
    const float* w_r0   = (const float*)d_in[12];
    const float* w_up1  = (const float*)d_in[13];
    const float* r1w1   = (const float*)d_in[14];
    const float* r1w2   = (const float*)d_in[15];
    const float* r1w3   = (const float*)d_in[16];
    const float* r1w4   = (const float*)d_in[17];
    const float* w_out1 = (const float*)d_in[18];
    const float* w_sc1  = (const float*)d_in[19];
    const float* w_m1   = (const float*)d_in[20];
    const float* w_m2   = (const float*)d_in[21];
    const int*   ei     = (const int*)d_in[22];
    const int*   batch  = (const int*)d_in[23];
    float* out = (float*)d_out;

    k_prep<<<64,256>>>(attrs, w_out0, w_up1, w_emb, w_up0, w_sc0);
    k_geom_hist<<<625,256>>>(pos, shifts, ei);
    k_scan<<<2,1024>>>(aener, batch);
    k_lut_build<<<dim3(NLUT/8,2),256>>>(r0w1,r0w2,r0w3,r0w4, r1w1,r1w2,r1w3,r1w4);
    k_pair_csr<<<PAIRB+625,256>>>(ei);
    k_int0<<<1184,256>>>(w_out0, w_r0, w_up1, batch);
    k_int1<<<1184,256>>>(w_out1, w_sc1, w_m1, w_m2, w_r0, batch);
    k_int1_bwd<<<1184,256>>>(w_up1, w_out0);
    k_bwd_edge<<<NE*32/256,256>>>(ei);
    k_force_node<<<NN/4,128>>>(out);
}

// round 17
// speedup vs baseline: 1.0726x; 1.0224x over previous
#include <cuda_runtime.h>
#include <math.h>

#define NE 160000
#define NN 10000
#define N64 (NN*64)
#define NLUT 1024
#define LUT_H   (5.0f/(NLUT-1))
#define LUT_INV ((NLUT-1)/5.0f)

#define S3f  1.7320508075688772f
#define IS3f 0.5773502691896258f
#define S5f  2.2360679774997896f
#define S15f 3.8729833462074170f
#define PIf  3.14159265358979323846f
#define K0C  (0.0625f)
#define K1C  (0.0625f/S3f)
#define K2C  (0.0625f/S5f)
#define K4N  (-0.0625f/S3f)
#define K9N  (0.0625f/S5f)

// ---------------- scratch ----------------
__device__ float d_r[NE];
__device__ float d_Y[NE*8];
__device__ float d_gvec[NE*3];

__device__ float d_lutR0[NLUT*192], d_lutD0[NLUT*192];
__device__ float d_lutR1[NLUT*192], d_lutD1[NLUT*192];
__device__ float2 d_P0[NLUT*192], d_PD0[NLUT*192];
__device__ float2 d_P1[NLUT*192], d_PD1[NLUT*192];

// CSR-ordered edge records: 12 floats = {other|sp<<16, li*192, w, eid|recv<<18, Y[8]}
__device__ float d_erec_r[NE*12];
__device__ float d_erec_s[NE*12];

__device__ int   d_sp[NN];
__device__ float d_hup0v[640];
__device__ float d_sc0v[640];
__device__ float d_h1_0[N64];
__device__ float d_hup1_0[N64];
__device__ float d_hup1_1[3*N64];
__device__ float d_hup1_2[5*N64];
__device__ float d_gagg1[3*N64];
__device__ float d_gh1_0[N64];
__device__ float d_gagg0_0[N64];
__device__ float d_gagg0_1[3*N64];
__device__ float d_gagg0_2[5*N64];
__device__ float d_W01[4096], d_W02[4096];
__device__ float d_e[48];
__device__ int   d_ctr[4];

// CSR
__device__ int d_deg_r[NN], d_deg_s[NN];
__device__ int d_off_r[NN+1], d_off_s[NN+1];
__device__ int d_cur_r[NN], d_cur_s[NN];

__device__ __forceinline__ float siluf(float x){ float s=1.f/(1.f+expf(-x)); return x*s; }
__device__ __forceinline__ float dsiluf(float x){ float s=1.f/(1.f+expf(-x)); return s*(1.f+x*(1.f-s)); }
__device__ __forceinline__ void lut_idx(float r, int& li, float& w){
    float u = fminf(r*LUT_INV, (float)(NLUT-1));
    li = (int)u; if (li > NLUT-2) li = NLUT-2;
    w = u - (float)li;
}
__device__ __forceinline__ float2 lerp2(const float2* __restrict__ P, int idx, float w){
    float4 p = *reinterpret_cast<const float4*>(P+idx);
    return make_float2(fmaf(w,p.y,p.x), fmaf(w,p.w,p.z));
}
__device__ __forceinline__ float warp_sum(float v){
    #pragma unroll
    for (int off=16;off>0;off>>=1) v += __shfl_xor_sync(0xffffffffu, v, off);
    return v;
}

// ---- fused prologue: zeroing + species + precW + prec_sp --------------------
__global__ void k_prep(const float* __restrict__ attrs,
                       const float* __restrict__ w_out0, const float* __restrict__ w_up1,
                       const float* __restrict__ w_emb, const float* __restrict__ w_up0,
                       const float* __restrict__ w_sc0){
    int tid = blockIdx.x*blockDim.x + threadIdx.x;
    int st = gridDim.x*blockDim.x;
    for (int j=tid;j<48;j+=st) d_e[j]=0.f;
    if (tid<4) d_ctr[tid]=0;
    for (int j=tid;j<NN;j+=st){ d_deg_r[j]=0; d_deg_s[j]=0; }
    for (int n=tid;n<NN;n+=st){
        int sp=0;
        for (int q=0;q<10;q++) if (attrs[n*10+q] > 0.5f) sp=q;
        d_sp[n]=sp;
    }
    for (int idx=tid; idx<8192; idx+=st){
        int l = idx>>12, rem = idx&4095, c = rem>>6, d2 = rem&63;
        const float* wo = w_out0 + (l+1)*4096;
        const float* wu = w_up1  + (l+1)*4096;
        float a=0.f;
        for (int d=0;d<64;d++) a = fmaf(wo[c*64+d], wu[d*64+d2], a);
        if (l==0) d_W01[c*64+d2]=a; else d_W02[c*64+d2]=a;
    }
    for (int idx=tid; idx<640; idx+=st){
        int sp = idx>>6, j = idx&63;
        float a=0.f, b=0.f;
        const float* wsc = w_sc0 + sp*4096;
        for (int c=0;c<64;c++){
            float we = w_emb[sp*64+c];
            a = fmaf(we, w_up0[c*64+j], a);
            b = fmaf(we, wsc[c*64+j], b);
        }
        d_hup0v[idx]=a; d_sc0v[idx]=b;
    }
}

__global__ void k_geom_hist(const float* __restrict__ pos, const float* __restrict__ shifts,
                            const int* __restrict__ ei){
    int e = blockIdx.x*blockDim.x + threadIdx.x;
    if (e >= NE) return;
    int s = ei[e], t = ei[NE+e];
    atomicAdd(&d_deg_r[t],1);
    atomicAdd(&d_deg_s[s],1);
    float vx = pos[t*3+0]-pos[s*3+0]+shifts[e*3+0];
    float vy = pos[t*3+1]-pos[s*3+1]+shifts[e*3+1];
    float vz = pos[t*3+2]-pos[s*3+2]+shifts[e*3+2];
    float r  = sqrtf(vx*vx+vy*vy+vz*vz + 1e-12f);
    d_r[e]=r;
    float inv = 1.0f/r;
    float x=vx*inv, y=vy*inv, z=vz*inv;
    d_Y[e*8+0]=S3f*y;  d_Y[e*8+1]=S3f*z;  d_Y[e*8+2]=S3f*x;
    d_Y[e*8+3]=S15f*x*y; d_Y[e*8+4]=S15f*y*z;
    d_Y[e*8+5]=0.5f*S5f*(3.f*z*z-1.f);
    d_Y[e*8+6]=S15f*x*z; d_Y[e*8+7]=0.5f*S15f*(x*x-y*y);
}

// two-block scan (r and s in parallel) + e0 accumulation in block 0 prologue
__global__ void k_scan(const float* __restrict__ aener, const int* __restrict__ batch){
    __shared__ int sh[1024];
    int t = threadIdx.x;
    int w = blockIdx.x;
    if (w==0){
        int n0 = t*10, n1 = min(n0+10, NN);
        if (n0 < NN){
            float acc=0.f; int bcur = batch[n0];
            for (int n=n0;n<n1;n++){
                int b = batch[n];
                if (b != bcur){ atomicAdd(&d_e[bcur], acc); acc=0.f; bcur=b; }
                acc += aener[d_sp[n]];
            }
            atomicAdd(&d_e[bcur], acc);
        }
    }
    int* deg = w? d_deg_s: d_deg_r;
    int* off = w? d_off_s: d_off_r;
    int* cur = w? d_cur_s: d_cur_r;
    int base = t*10, s=0;
    #pragma unroll
    for (int i=0;i<10;i++){ int idx=base+i; if (idx<NN) s+=deg[idx]; }
    sh[t]=s;
    __syncthreads();
    for (int d=1; d<1024; d<<=1){
        int v = (t>=d)? sh[t-d]:0;
        __syncthreads();
        sh[t]+=v;
        __syncthreads();
    }
    int run = sh[t]-s;
    #pragma unroll
    for (int i=0;i<10;i++){ int idx=base+i; if (idx<NN){ off[idx]=run; cur[idx]=run; run+=deg[idx]; } }
    if (t==0) off[NN]=NE;
}

// ------------- LUT build: both MLPs, 8 rows/block, dual-number ---------------
#define MM64x2(DST,SRC) do{ \
    _Pragma("unroll") for(int i=0;i<2;i++) DST[i]=0.f; \
    _Pragma("unroll") for(int k0=0;k0<64;k0+=4){ \
        _Pragma("unroll") for(int i=0;i<2;i++){ \
            float4 a4=*(const float4*)&SRC[r0+i][k0]; \
            DST[i]=fmaf(a4.x,wc[k0],DST[i]); DST[i]=fmaf(a4.y,wc[k0+1],DST[i]); \
            DST[i]=fmaf(a4.z,wc[k0+2],DST[i]); DST[i]=fmaf(a4.w,wc[k0+3],DST[i]); } } \
}while(0)
#define FILLW() _Pragma("unroll") for(int k=0;k<64;k++) wc[k]=sW[k*65+j]

__global__ void __launch_bounds__(256) k_lut_build(
        const float* __restrict__ w1a, const float* __restrict__ w2a,
        const float* __restrict__ w3a, const float* __restrict__ w4a,
        const float* __restrict__ w1b, const float* __restrict__ w2b,
        const float* __restrict__ w3b, const float* __restrict__ w4b){
    int which = blockIdx.y;
    const float* w1 = which? w1b : w1a;
    const float* w2 = which? w2b : w2a;
    const float* w3 = which? w3b : w3a;
    const float* w4 = which? w4b : w4a;
    int w4s = which? 832 : 192;
    int cbs[3]; cbs[0]=0; cbs[1]= which? 256:64; cbs[2]= which? 576:128;
    float kps[3]; kps[0]=K0C; kps[1]= which? K4N:K1C; kps[2]= which? K9N:K2C;
    __shared__ float sV[8][64];
    __shared__ float sT[8][64];
    __shared__ float sW[64*65];
    int tid=threadIdx.x, j=tid&63, r0=(tid>>6)*2;
    int row0=blockIdx.x*8;
    float* LR = which? d_lutR1 : d_lutR0;
    float* LD = which? d_lutD1 : d_lutD0;
    if (tid < 64){
        int rr=tid>>3, q=tid&7;
        float rv = (float)(row0+rr)*LUT_H;
        float rs = fmaxf(rv, 1e-6f);
        float inv = 1.0f/rs;
        float uu = rs*0.2f;
        float u2=uu*uu, u4=u2*u2, u5=u4*uu, u6=u5*uu, u7=u6*uu;
        float fc  = 1.f - 21.f*u5 + 35.f*u6 - 15.f*u7;
        float dfc = (-105.f*u4 + 210.f*u5 - 105.f*u6)*0.2f;
        if (uu >= 1.0f){ fc=0.f; dfc=0.f; }
        float a = (float)(q+1)*(PIf/5.0f);
        float sa=sinf(a*rs), ca=cosf(a*rs);
        float c0 = sqrtf(0.4f);
        sV[rr][q] = c0*sa*inv*fc;
        sT[rr][q] = c0*((a*ca*inv - sa*inv*inv)*fc + sa*inv*dfc);
    }
    __syncthreads();
    float aV[2], aT[2], wc[64];
    #pragma unroll
    for (int i=0;i<2;i++){ aV[i]=0.f; aT[i]=0.f; }
    #pragma unroll
    for (int k=0;k<8;k++){
        float w=w1[k*64+j];
        #pragma unroll
        for (int i=0;i<2;i++){ aV[i]=fmaf(sV[r0+i][k],w,aV[i]); aT[i]=fmaf(sT[r0+i][k],w,aT[i]); }
    }
    __syncthreads();
    #pragma unroll
    for (int i=0;i<2;i++){ float z=aV[i]; sV[r0+i][j]=siluf(z); sT[r0+i][j]=dsiluf(z)*aT[i]; }
    for(int idx=tid; idx<4096; idx+=256){ int a_=idx>>6, b_=idx&63; sW[a_*65+b_]=w2[idx]; }
    __syncthreads();
    FILLW();
    MM64x2(aV, sV);
    MM64x2(aT, sT);
    __syncthreads();
    #pragma unroll
    for (int i=0;i<2;i++){ float z=aV[i]; sV[r0+i][j]=siluf(z); sT[r0+i][j]=dsiluf(z)*aT[i]; }
    for(int idx=tid; idx<4096; idx+=256){ int a_=idx>>6, b_=idx&63; sW[a_*65+b_]=w3[idx]; }
    __syncthreads();
    FILLW();
    MM64x2(aV, sV);
    MM64x2(aT, sT);
    __syncthreads();
    #pragma unroll
    for (int i=0;i<2;i++){ float z=aV[i]; sV[r0+i][j]=siluf(z); sT[r0+i][j]=dsiluf(z)*aT[i]; }
    for (int p=0;p<3;p++){
        for(int idx=tid; idx<4096; idx+=256){ int a_=idx>>6, b_=idx&63; sW[a_*65+b_]=w4[a_*w4s+cbs[p]+b_]; }
        __syncthreads();
        FILLW();
        MM64x2(aV, sV);
        MM64x2(aT, sT);
        float kp = kps[p];
        #pragma unroll
        for (int i=0;i<2;i++){
            LR[(row0+r0+i)*192 + p*64 + j] = kp*aV[i];
            LD[(row0+r0+i)*192 + p*64 + j] = kp*aT[i];
        }
        __syncthreads();
    }
}

// ---- fused: pair-table build + CSR fill (independent works, one launch) -----
#define PAIRB (NLUT*192/256)
__global__ void k_pair_csr(const int* __restrict__ ei){
    int b = blockIdx.x;
    if (b < PAIRB){
        int idx = b*256 + threadIdx.x;
        int li = idx/192;
        int nidx = (li < NLUT-1)? idx+192 : idx;
        float v;
        v = d_lutR0[idx]; d_P0[idx]  = make_float2(v, d_lutR0[nidx]-v);
        v = d_lutD0[idx]; d_PD0[idx] = make_float2(v, d_lutD0[nidx]-v);
        v = d_lutR1[idx]; d_P1[idx]  = make_float2(v, d_lutR1[nidx]-v);
        v = d_lutD1[idx]; d_PD1[idx] = make_float2(v, d_lutD1[nidx]-v);
        return;
    }
    int e = (b-PAIRB)*256 + threadIdx.x;
    if (e >= NE) return;
    int s = ei[e], t = ei[NE+e];
    int sp_s = d_sp[s], sp_t = d_sp[t];
    int li; float w; lut_idx(d_r[e], li, w);
    float y[8];
    #pragma unroll
    for (int i=0;i<8;i++) y[i]=d_Y[e*8+i];
    int p = atomicAdd(&d_cur_r[t],1);
    float* R = d_erec_r + p*12;
    R[0]=__int_as_float(s | (sp_s<<16)); R[1]=__int_as_float(li*192); R[2]=w;
    R[3]=__int_as_float((int)((unsigned)e | ((unsigned)t<<18)));
    #pragma unroll
    for (int i=0;i<8;i++) R[4+i]=y[i];
    int q = atomicAdd(&d_cur_s[s],1);
    R = d_erec_s + q*12;
    R[0]=__int_as_float(t | (sp_t<<16)); R[1]=__int_as_float(li*192); R[2]=w;
    R[3]=__int_as_float((int)((unsigned)e | ((unsigned)s<<18)));
    #pragma unroll
    for (int i=0;i<8;i++) R[4+i]=y[i];
}

// ------------------ interaction 0: dynamic queue, 2ch/lane -------------------
#define INT0_EDGE(Rq) { \
    float4 rh=(Rq)[0], ya=(Rq)[1], yb=(Rq)[2]; \
    int v=__float_as_int(rh.x); int spv=v>>16; int base=__float_as_int(rh.y); float w=rh.z; \
    float2 hup=*reinterpret_cast<const float2*>(&sHup[spv*64+c0]); \
    float2 p=lerp2(d_P0, base+c0, w); \
    a0.x=fmaf(hup.x,p.x,a0.x); a0.y=fmaf(hup.y,p.y,a0.y); \
    p=lerp2(d_P0, base+64+c0, w); \
    float m1x=hup.x*p.x, m1y=hup.y*p.y; \
    a1[0].x=fmaf(m1x,ya.x,a1[0].x); a1[0].y=fmaf(m1y,ya.x,a1[0].y); \
    a1[1].x=fmaf(m1x,ya.y,a1[1].x); a1[1].y=fmaf(m1y,ya.y,a1[1].y); \
    a1[2].x=fmaf(m1x,ya.z,a1[2].x); a1[2].y=fmaf(m1y,ya.z,a1[2].y); \
    p=lerp2(d_P0, base+128+c0, w); \
    float m2x=hup.x*p.x, m2y=hup.y*p.y; \
    a2[0].x=fmaf(m2x,ya.w,a2[0].x); a2[0].y=fmaf(m2y,ya.w,a2[0].y); \
    a2[1].x=fmaf(m2x,yb.x,a2[1].x); a2[1].y=fmaf(m2y,yb.x,a2[1].y); \
    a2[2].x=fmaf(m2x,yb.y,a2[2].x); a2[2].y=fmaf(m2y,yb.y,a2[2].y); \
    a2[3].x=fmaf(m2x,yb.z,a2[3].x); a2[3].y=fmaf(m2y,yb.z,a2[3].y); \
    a2[4].x=fmaf(m2x,yb.w,a2[4].x); a2[4].y=fmaf(m2y,yb.w,a2[4].y); \
}

__global__ void __launch_bounds__(256) k_int0(const float* __restrict__ w_out0,
                       const float* __restrict__ w_r0, const float* __restrict__ w_up1,
                       const int* __restrict__ batch){
    int wid=threadIdx.x>>5, l=threadIdx.x&31, c0=l*2;
    __shared__ float sm[8][640];
    __shared__ float sHup[640];
    __shared__ int sBase;
    for (int i=threadIdx.x;i<640;i+=256) sHup[i]=d_hup0v[i];
    float* sA0=sm[wid]; float* sA1=sA0+64; float* sA2=sA1+192; float* sh1=sA2+320;
    for(;;){
        __syncthreads();
        if (threadIdx.x==0) sBase = atomicAdd(&d_ctr[0],1);
        __syncthreads();
        int g = sBase;
        if (g >= NN/8) break;
        int n = g*8 + wid;
        int sp=d_sp[n];
        float2 a0=make_float2(0.f,0.f), a1[3], a2[5];
        #pragma unroll
        for (int i=0;i<3;i++) a1[i]=make_float2(0.f,0.f);
        #pragma unroll
        for (int i=0;i<5;i++) a2[i]=make_float2(0.f,0.f);
        int b0=d_off_r[n], b1=d_off_r[n+1];
        int q=b0;
        for (; q+1<b1; q+=2){
            const float4* R1 = reinterpret_cast<const float4*>(d_erec_r+q*12);
            const float4* R2 = reinterpret_cast<const float4*>(d_erec_r+(q+1)*12);
            INT0_EDGE(R1);
            INT0_EDGE(R2);
        }
        if (q<b1){
            const float4* R1 = reinterpret_cast<const float4*>(d_erec_r+q*12);
            INT0_EDGE(R1);
        }
        sA0[c0]=a0.x; sA0[c0+1]=a0.y;
        #pragma unroll
        for (int i=0;i<3;i++){ sA1[i*64+c0]=a1[i].x; sA1[i*64+c0+1]=a1[i].y; }
        #pragma unroll
        for (int i=0;i<5;i++){ sA2[i*64+c0]=a2[i].x; sA2[i*64+c0+1]=a2[i].y; }
        __syncwarp();
        float2 acc=*reinterpret_cast<const float2*>(&d_sc0v[sp*64+c0]);
        for (int c=0;c<64;c++){
            float va=sA0[c];
            float2 wo=*reinterpret_cast<const float2*>(&w_out0[c*64+c0]);
            acc.x = fmaf(va,wo.x,acc.x);
            acc.y = fmaf(va,wo.y,acc.y);
        }
        *reinterpret_cast<float2*>(&d_h1_0[n*64+c0]) = acc;
        sh1[c0]=acc.x; sh1[c0+1]=acc.y;
        float2 wr=*reinterpret_cast<const float2*>(&w_r0[c0]);
        float ev = warp_sum(acc.x*wr.x + acc.y*wr.y);
        if (l==0) atomicAdd(&d_e[16+batch[n]], ev);
        __syncwarp();
        float2 au=make_float2(0.f,0.f);
        for (int c=0;c<64;c++){
            float vh=sh1[c];
            float2 wu=*reinterpret_cast<const float2*>(&w_up1[c*64+c0]);
            au.x=fmaf(vh,wu.x,au.x); au.y=fmaf(vh,wu.y,au.y);
        }
        *reinterpret_cast<float2*>(&d_hup1_0[n*64+c0]) = au;
        float2 bb[3];
        #pragma unroll
        for (int i=0;i<3;i++) bb[i]=make_float2(0.f,0.f);
        for (int c=0;c<64;c++){
            float2 w2=*reinterpret_cast<const float2*>(&d_W01[c*64+c0]);
            #pragma unroll
            for (int i=0;i<3;i++){
                float v=sA1[i*64+c];
                bb[i].x=fmaf(v,w2.x,bb[i].x); bb[i].y=fmaf(v,w2.y,bb[i].y);
            }
        }
        #pragma unroll
        for (int i=0;i<3;i++) *reinterpret_cast<float2*>(&d_hup1_1[i*N64+n*64+c0]) = bb[i];
        float2 ee[5];
        #pragma unroll
        for (int i=0;i<5;i++) ee[i]=make_float2(0.f,0.f);
        for (int c=0;c<64;c++){
            float2 w2=*reinterpret_cast<const float2*>(&d_W02[c*64+c0]);
            #pragma unroll
            for (int i=0;i<5;i++){
                float v=sA2[i*64+c];
                ee[i].x=fmaf(v,w2.x,ee[i].x); ee[i].y=fmaf(v,w2.y,ee[i].y);
            }
        }
        #pragma unroll
        for (int i=0;i<5;i++) *reinterpret_cast<float2*>(&d_hup1_2[i*N64+n*64+c0]) = ee[i];
    }
}

// ------------------ interaction 1: dynamic queue, 2ch/lane -------------------
#define INT1_EDGE(Rq) { \
    float4 rh=(Rq)[0], ya=(Rq)[1], yb=(Rq)[2]; \
    int s=__float_as_int(rh.x)&0xFFFF; int base=__float_as_int(rh.y); float w=rh.z; \
    float2 h0=*reinterpret_cast<const float2*>(&d_hup1_0[s*64+c0]); \
    float2 p=lerp2(d_P1, base+c0, w); \
    a0.x=fmaf(h0.x,p.x,a0.x); a0.y=fmaf(h0.y,p.y,a0.y); \
    float2 h10=*reinterpret_cast<const float2*>(&d_hup1_1[0*N64+s*64+c0]); \
    float2 h11=*reinterpret_cast<const float2*>(&d_hup1_1[1*N64+s*64+c0]); \
    float2 h12=*reinterpret_cast<const float2*>(&d_hup1_1[2*N64+s*64+c0]); \
    float S1x = ya.x*h10.x + ya.y*h11.x + ya.z*h12.x; \
    float S1y = ya.x*h10.y + ya.y*h11.y + ya.z*h12.y; \
    p=lerp2(d_P1, base+64+c0, w); \
    a1.x=fmaf(S1x,p.x,a1.x); a1.y=fmaf(S1y,p.y,a1.y); \
    float2 h20=*reinterpret_cast<const float2*>(&d_hup1_2[0*N64+s*64+c0]); \
    float2 h21=*reinterpret_cast<const float2*>(&d_hup1_2[1*N64+s*64+c0]); \
    float2 h22=*reinterpret_cast<const float2*>(&d_hup1_2[2*N64+s*64+c0]); \
    float2 h23=*reinterpret_cast<const float2*>(&d_hup1_2[3*N64+s*64+c0]); \
    float2 h24=*reinterpret_cast<const float2*>(&d_hup1_2[4*N64+s*64+c0]); \
    float S2x = ya.w*h20.x + yb.x*h21.x + yb.y*h22.x + yb.z*h23.x + yb.w*h24.x; \
    float S2y = ya.w*h20.y + yb.x*h21.y + yb.y*h22.y + yb.z*h23.y + yb.w*h24.y; \
    p=lerp2(d_P1, base+128+c0, w); \
    a2.x=fmaf(S2x,p.x,a2.x); a2.y=fmaf(S2y,p.y,a2.y); \
}

__global__ void __launch_bounds__(256) k_int1(const float* __restrict__ w_out1,
                       const float* __restrict__ w_sc1, const float* __restrict__ w_m1,
                       const float* __restrict__ w_m2, const float* __restrict__ w_r0,
                       const int* __restrict__ batch){
    int wid=threadIdx.x>>5, l=threadIdx.x&31, c0=l*2;
    __shared__ float sm[8][448];
    __shared__ int sBase;
    float* sA0=sm[wid]; float* sA1=sA0+64; float* sA2=sA1+64; float* sh1=sA2+64;
    float* sh2=sh1+64; float* sg2=sh2+64; float* sdz=sg2+64; float* sv=sdz+16;
    const float* wo0 = w_out1;
    const float* wo4 = w_out1 + 4*4096;
    const float* wo9 = w_out1 + 9*4096;
    for(;;){
        __syncthreads();
        if (threadIdx.x==0) sBase = atomicAdd(&d_ctr[1],1);
        __syncthreads();
        int g = sBase;
        if (g >= NN/8) break;
        int n = g*8 + wid;
        int sp=d_sp[n];
        float2 a0=make_float2(0.f,0.f), a1=make_float2(0.f,0.f), a2=make_float2(0.f,0.f);
        int b0=d_off_r[n], b1=d_off_r[n+1];
        int q=b0;
        for (; q+1<b1; q+=2){
            const float4* R1 = reinterpret_cast<const float4*>(d_erec_r+q*12);
            const float4* R2 = reinterpret_cast<const float4*>(d_erec_r+(q+1)*12);
            INT1_EDGE(R1);
            INT1_EDGE(R2);
        }
        if (q<b1){
            const float4* R1 = reinterpret_cast<const float4*>(d_erec_r+q*12);
            INT1_EDGE(R1);
        }
        sA0[c0]=a0.x; sA0[c0+1]=a0.y;
        sA1[c0]=a1.x; sA1[c0+1]=a1.y;
        sA2[c0]=a2.x; sA2[c0+1]=a2.y;
        float2 h1v=*reinterpret_cast<const float2*>(&d_h1_0[n*64+c0]);
        sh1[c0]=h1v.x; sh1[c0+1]=h1v.y;
        __syncwarp();
        const float* wsc = w_sc1 + sp*4096;
        float2 h2=make_float2(0.f,0.f);
        for (int c=0;c<64;c++){
            float v0=sA0[c], v1=sA1[c], v2=sA2[c], vh=sh1[c];
            float2 wa=*reinterpret_cast<const float2*>(&wo0[c*64+c0]);
            float2 wb=*reinterpret_cast<const float2*>(&wo4[c*64+c0]);
            float2 wcv=*reinterpret_cast<const float2*>(&wo9[c*64+c0]);
            float2 wd=*reinterpret_cast<const float2*>(&wsc[c*64+c0]);
            h2.x = fmaf(v0,wa.x,fmaf(v1,wb.x,fmaf(v2,wcv.x,fmaf(vh,wd.x,h2.x))));
            h2.y = fmaf(v0,wa.y,fmaf(v1,wb.y,fmaf(v2,wcv.y,fmaf(vh,wd.y,h2.y))));
        }
        sh2[c0]=h2.x; sh2[c0+1]=h2.y;
        __syncwarp();
        if (l < 16){
            float z=0.f;
            for (int d=0;d<64;d++) z = fmaf(sh2[d], w_m1[d*16+l], z);
            float s=1.f/(1.f+expf(-z));
            sv[l]  = z*s*w_m2[l];
            sdz[l] = s*(1.f+z*(1.f-s))*w_m2[l];
        }
        __syncwarp();
        if (l==0){
            float t=0.f;
            for (int q2=0;q2<16;q2++) t+=sv[q2];
            atomicAdd(&d_e[32+batch[n]], t);
        }
        float2 gh2=make_float2(0.f,0.f);
        #pragma unroll 4
        for (int q2=0;q2<16;q2++){
            float dz=sdz[q2];
            gh2.x = fmaf(w_m1[c0*16+q2], dz, gh2.x);
            gh2.y = fmaf(w_m1[(c0+1)*16+q2], dz, gh2.y);
        }
        sg2[c0]=gh2.x; sg2[c0+1]=gh2.y;
        __syncwarp();
        float2 wr=*reinterpret_cast<const float2*>(&w_r0[c0]);
        float2 ga0=make_float2(0.f,0.f), ga1=make_float2(0.f,0.f), ga2=make_float2(0.f,0.f);
        float2 gh1=wr;
        for (int d=0;d<64;d+=4){
            float4 g4 = *reinterpret_cast<const float4*>(&sg2[d]);
            float4 wA = *reinterpret_cast<const float4*>(&wo0[c0*64+d]);
            float4 wB = *reinterpret_cast<const float4*>(&wo0[(c0+1)*64+d]);
            ga0.x = fmaf(wA.x,g4.x,fmaf(wA.y,g4.y,fmaf(wA.z,g4.z,fmaf(wA.w,g4.w,ga0.x))));
            ga0.y = fmaf(wB.x,g4.x,fmaf(wB.y,g4.y,fmaf(wB.z,g4.z,fmaf(wB.w,g4.w,ga0.y))));
            wA = *reinterpret_cast<const float4*>(&wo4[c0*64+d]);
            wB = *reinterpret_cast<const float4*>(&wo4[(c0+1)*64+d]);
            ga1.x = fmaf(wA.x,g4.x,fmaf(wA.y,g4.y,fmaf(wA.z,g4.z,fmaf(wA.w,g4.w,ga1.x))));
            ga1.y = fmaf(wB.x,g4.x,fmaf(wB.y,g4.y,fmaf(wB.z,g4.z,fmaf(wB.w,g4.w,ga1.y))));
            wA = *reinterpret_cast<const float4*>(&wo9[c0*64+d]);
            wB = *reinterpret_cast<const float4*>(&wo9[(c0+1)*64+d]);
            ga2.x = fmaf(wA.x,g4.x,fmaf(wA.y,g4.y,fmaf(wA.z,g4.z,fmaf(wA.w,g4.w,ga2.x))));
            ga2.y = fmaf(wB.x,g4.x,fmaf(wB.y,g4.y,fmaf(wB.z,g4.z,fmaf(wB.w,g4.w,ga2.y))));
            wA = *reinterpret_cast<const float4*>(&wsc[c0*64+d]);
            wB = *reinterpret_cast<const float4*>(&wsc[(c0+1)*64+d]);
            gh1.x = fmaf(wA.x,g4.x,fmaf(wA.y,g4.y,fmaf(wA.z,g4.z,fmaf(wA.w,g4.w,gh1.x))));
            gh1.y = fmaf(wB.x,g4.x,fmaf(wB.y,g4.y,fmaf(wB.z,g4.z,fmaf(wB.w,g4.w,gh1.y))));
        }
        *reinterpret_cast<float2*>(&d_gagg1[n*64+c0])=ga0;
        *reinterpret_cast<float2*>(&d_gagg1[N64+n*64+c0])=ga1;
        *reinterpret_cast<float2*>(&d_gagg1[2*N64+n*64+c0])=ga2;
        *reinterpret_cast<float2*>(&d_gh1_0[n*64+c0])=gh1;
    }
}

// --------------- int1 backward: dynamic queue, 2ch/lane ----------------------
#define BWD1_EDGE(Rq) { \
    float4 rh=(Rq)[0], ya=(Rq)[1], yb=(Rq)[2]; \
    int t=__float_as_int(rh.x)&0xFFFF; int base=__float_as_int(rh.y); float w=rh.z; \
    float2 g0=*reinterpret_cast<const float2*>(&d_gagg1[t*64+c0]); \
    float2 g1=*reinterpret_cast<const float2*>(&d_gagg1[N64+t*64+c0]); \
    float2 g2=*reinterpret_cast<const float2*>(&d_gagg1[2*N64+t*64+c0]); \
    float2 p=lerp2(d_P1, base+c0, w); \
    g0a.x=fmaf(p.x,g0.x,g0a.x); g0a.y=fmaf(p.y,g0.y,g0a.y); \
    p=lerp2(d_P1, base+64+c0, w); \
    float a1x=p.x*g1.x, a1y=p.y*g1.y; \
    g1a[0].x=fmaf(a1x,ya.x,g1a[0].x); g1a[0].y=fmaf(a1y,ya.x,g1a[0].y); \
    g1a[1].x=fmaf(a1x,ya.y,g1a[1].x); g1a[1].y=fmaf(a1y,ya.y,g1a[1].y); \
    g1a[2].x=fmaf(a1x,ya.z,g1a[2].x); g1a[2].y=fmaf(a1y,ya.z,g1a[2].y); \
    p=lerp2(d_P1, base+128+c0, w); \
    float a2x=p.x*g2.x, a2y=p.y*g2.y; \
    g2a[0].x=fmaf(a2x,ya.w,g2a[0].x); g2a[0].y=fmaf(a2y,ya.w,g2a[0].y); \
    g2a[1].x=fmaf(a2x,yb.x,g2a[1].x); g2a[1].y=fmaf(a2y,yb.x,g2a[1].y); \
    g2a[2].x=fmaf(a2x,yb.y,g2a[2].x); g2a[2].y=fmaf(a2y,yb.y,g2a[2].y); \
    g2a[3].x=fmaf(a2x,yb.z,g2a[3].x); g2a[3].y=fmaf(a2y,yb.z,g2a[3].y); \
    g2a[4].x=fmaf(a2x,yb.w,g2a[4].x); g2a[4].y=fmaf(a2y,yb.w,g2a[4].y); \
}

__global__ void __launch_bounds__(256) k_int1_bwd(const float* __restrict__ w_up1,
                           const float* __restrict__ w_out0){
    int wid=threadIdx.x>>5, l=threadIdx.x&31, c0=l*2;
    __shared__ float sm[8][640];
    __shared__ int sBase;
    float* sg0=sm[wid]; float* sg1=sg0+64; float* sg2=sg1+192; float* sgh1=sg2+320;
    for(;;){
        __syncthreads();
        if (threadIdx.x==0) sBase = atomicAdd(&d_ctr[2],1);
        __syncthreads();
        int g = sBase;
        if (g >= NN/8) break;
        int n = g*8 + wid;
        float2 g0a=make_float2(0.f,0.f), g1a[3], g2a[5];
        #pragma unroll
        for (int i=0;i<3;i++) g1a[i]=make_float2(0.f,0.f);
        #pragma unroll
        for (int i=0;i<5;i++) g2a[i]=make_float2(0.f,0.f);
        int b0=d_off_s[n], b1=d_off_s[n+1];
        int q=b0;
        for (; q+1<b1; q+=2){
            const float4* R1 = reinterpret_cast<const float4*>(d_erec_s+q*12);
            const float4* R2 = reinterpret_cast<const float4*>(d_erec_s+(q+1)*12);
            BWD1_EDGE(R1);
            BWD1_EDGE(R2);
        }
        if (q<b1){
            const float4* R1 = reinterpret_cast<const float4*>(d_erec_s+q*12);
            BWD1_EDGE(R1);
        }
        sg0[c0]=g0a.x; sg0[c0+1]=g0a.y;
        #pragma unroll
        for (int i=0;i<3;i++){ sg1[i*64+c0]=g1a[i].x; sg1[i*64+c0+1]=g1a[i].y; }
        #pragma unroll
        for (int i=0;i<5;i++){ sg2[i*64+c0]=g2a[i].x; sg2[i*64+c0+1]=g2a[i].y; }
        __syncwarp();
        float2 gh1=*reinterpret_cast<const float2*>(&d_gh1_0[n*64+c0]);
        for (int d=0;d<64;d+=4){
            float4 g4 = *reinterpret_cast<const float4*>(&sg0[d]);
            float4 wA = *reinterpret_cast<const float4*>(&w_up1[c0*64+d]);
            float4 wB = *reinterpret_cast<const float4*>(&w_up1[(c0+1)*64+d]);
            gh1.x = fmaf(wA.x,g4.x,fmaf(wA.y,g4.y,fmaf(wA.z,g4.z,fmaf(wA.w,g4.w,gh1.x))));
            gh1.y = fmaf(wB.x,g4.x,fmaf(wB.y,g4.y,fmaf(wB.z,g4.z,fmaf(wB.w,g4.w,gh1.y))));
        }
        sgh1[c0]=gh1.x; sgh1[c0+1]=gh1.y;
        __syncwarp();
        float2 ga=make_float2(0.f,0.f);
        for (int d=0;d<64;d+=4){
            float4 g4 = *reinterpret_cast<const float4*>(&sgh1[d]);
            float4 wA = *reinterpret_cast<const float4*>(&w_out0[c0*64+d]);
            float4 wB = *reinterpret_cast<const float4*>(&w_out0[(c0+1)*64+d]);
            ga.x = fmaf(wA.x,g4.x,fmaf(wA.y,g4.y,fmaf(wA.z,g4.z,fmaf(wA.w,g4.w,ga.x))));
            ga.y = fmaf(wB.x,g4.x,fmaf(wB.y,g4.y,fmaf(wB.z,g4.z,fmaf(wB.w,g4.w,ga.y))));
        }
        *reinterpret_cast<float2*>(&d_gagg0_0[n*64+c0])=ga;
        float2 bb[3];
        #pragma unroll
        for (int i=0;i<3;i++) bb[i]=make_float2(0.f,0.f);
        for (int d=0;d<64;d+=4){
            float4 wA = *reinterpret_cast<const float4*>(&d_W01[c0*64+d]);
            float4 wB = *reinterpret_cast<const float4*>(&d_W01[(c0+1)*64+d]);
            #pragma unroll
            for (int i=0;i<3;i++){
                float4 g4 = *reinterpret_cast<const float4*>(&sg1[i*64+d]);
                bb[i].x = fmaf(wA.x,g4.x,fmaf(wA.y,g4.y,fmaf(wA.z,g4.z,fmaf(wA.w,g4.w,bb[i].x))));
                bb[i].y = fmaf(wB.x,g4.x,fmaf(wB.y,g4.y,fmaf(wB.z,g4.z,fmaf(wB.w,g4.w,bb[i].y))));
            }
        }
        #pragma unroll
        for (int i=0;i<3;i++) *reinterpret_cast<float2*>(&d_gagg0_1[i*N64+n*64+c0])=bb[i];
        float2 cc[5];
        #pragma unroll
        for (int i=0;i<5;i++) cc[i]=make_float2(0.f,0.f);
        for (int d=0;d<64;d+=4){
            float4 wA = *reinterpret_cast<const float4*>(&d_W02[c0*64+d]);
            float4 wB = *reinterpret_cast<const float4*>(&d_W02[(c0+1)*64+d]);
            #pragma unroll
            for (int i=0;i<5;i++){
                float4 g4 = *reinterpret_cast<const float4*>(&sg2[i*64+d]);
                cc[i].x = fmaf(wA.x,g4.x,fmaf(wA.y,g4.y,fmaf(wA.z,g4.z,fmaf(wA.w,g4.w,cc[i].x))));
                cc[i].y = fmaf(wB.x,g4.x,fmaf(wB.y,g4.y,fmaf(wB.z,g4.z,fmaf(wB.w,g4.w,cc[i].y))));
            }
        }
        #pragma unroll
        for (int i=0;i<5;i++) *reinterpret_cast<float2*>(&d_gagg0_2[i*N64+n*64+c0])=cc[i];
    }
}

// --------- backward edge pass: warp-per-CSR-slot, receiver-ordered -----------
__global__ void k_bwd_edge(){
    int gtid = blockIdx.x*blockDim.x + threadIdx.x;
    int q = gtid>>5, lane = gtid&31, c0=lane*2;
    const float4* Rq = reinterpret_cast<const float4*>(d_erec_r+q*12);
    float4 rh=Rq[0], yA=Rq[1], yB=Rq[2];
    int v0=__float_as_int(rh.x); int s=v0&0xFFFF, sp_s=v0>>16;
    int base=__float_as_int(rh.y); float w=rh.z;
    unsigned ve=(unsigned)__float_as_int(rh.w); int e=(int)(ve&0x3FFFFu); int t=(int)(ve>>18);
    float y[8]={yA.x,yA.y,yA.z,yA.w,yB.x,yB.y,yB.z,yB.w};
    float r = ((float)(base/192) + w)*LUT_H;
    float tY[8]={0,0,0,0,0,0,0,0};
    float gr=0.f;
    // ---- layer 1 backward ----
    {
        float2 g0=*reinterpret_cast<const float2*>(&d_gagg1[t*64+c0]);
        float2 g1=*reinterpret_cast<const float2*>(&d_gagg1[N64+t*64+c0]);
        float2 g2=*reinterpret_cast<const float2*>(&d_gagg1[2*N64+t*64+c0]);
        float2 h0=*reinterpret_cast<const float2*>(&d_hup1_0[s*64+c0]);
        float2 h1v[3], h2v[5];
        #pragma unroll
        for (int i=0;i<3;i++) h1v[i]=*reinterpret_cast<const float2*>(&d_hup1_1[i*N64+s*64+c0]);
        #pragma unroll
        for (int i=0;i<5;i++) h2v[i]=*reinterpret_cast<const float2*>(&d_hup1_2[i*N64+s*64+c0]);
        float s1x=y[0]*h1v[0].x+y[1]*h1v[1].x+y[2]*h1v[2].x;
        float s1y=y[0]*h1v[0].y+y[1]*h1v[1].y+y[2]*h1v[2].y;
        float s2x=y[3]*h2v[0].x+y[4]*h2v[1].x+y[5]*h2v[2].x+y[6]*h2v[3].x+y[7]*h2v[4].x;
        float s2y=y[3]*h2v[0].y+y[4]*h2v[1].y+y[5]*h2v[2].y+y[6]*h2v[3].y+y[7]*h2v[4].y;
        float2 pd=lerp2(d_PD1, base+c0, w);
        gr = fmaf(pd.x, h0.x*g0.x, gr); gr = fmaf(pd.y, h0.y*g0.y, gr);
        pd=lerp2(d_PD1, base+64+c0, w);
        gr = fmaf(pd.x, s1x*g1.x, gr); gr = fmaf(pd.y, s1y*g1.y, gr);
        pd=lerp2(d_PD1, base+128+c0, w);
        gr = fmaf(pd.x, s2x*g2.x, gr); gr = fmaf(pd.y, s2y*g2.y, gr);
        float2 p=lerp2(d_P1, base+64+c0, w);
        float a1x=p.x*g1.x, a1y=p.y*g1.y;
        #pragma unroll
        for (int i=0;i<3;i++) tY[i] += a1x*h1v[i].x + a1y*h1v[i].y;
        p=lerp2(d_P1, base+128+c0, w);
        float a2x=p.x*g2.x, a2y=p.y*g2.y;
        #pragma unroll
        for (int i=0;i<5;i++) tY[3+i] += a2x*h2v[i].x + a2y*h2v[i].y;
    }
    // ---- layer 0 backward ----
    {
        float2 hp=*reinterpret_cast<const float2*>(&d_hup0v[sp_s*64+c0]);
        float2 ga0=*reinterpret_cast<const float2*>(&d_gagg0_0[t*64+c0]);
        float2 ga1[3], ga2[5];
        #pragma unroll
        for (int i=0;i<3;i++) ga1[i]=*reinterpret_cast<const float2*>(&d_gagg0_1[i*N64+t*64+c0]);
        #pragma unroll
        for (int i=0;i<5;i++) ga2[i]=*reinterpret_cast<const float2*>(&d_gagg0_2[i*N64+t*64+c0]);
        float s1x=y[0]*ga1[0].x+y[1]*ga1[1].x+y[2]*ga1[2].x;
        float s1y=y[0]*ga1[0].y+y[1]*ga1[1].y+y[2]*ga1[2].y;
        float s2x=y[3]*ga2[0].x+y[4]*ga2[1].x+y[5]*ga2[2].x+y[6]*ga2[3].x+y[7]*ga2[4].x;
        float s2y=y[3]*ga2[0].y+y[4]*ga2[1].y+y[5]*ga2[2].y+y[6]*ga2[3].y+y[7]*ga2[4].y;
        float2 pd=lerp2(d_PD0, base+c0, w);
        gr = fmaf(pd.x, hp.x*ga0.x, gr); gr = fmaf(pd.y, hp.y*ga0.y, gr);
        pd=lerp2(d_PD0, base+64+c0, w);
        gr = fmaf(pd.x, hp.x*s1x, gr); gr = fmaf(pd.y, hp.y*s1y, gr);
        pd=lerp2(d_PD0, base+128+c0, w);
        gr = fmaf(pd.x, hp.x*s2x, gr); gr = fmaf(pd.y, hp.y*s2y, gr);
        float2 p=lerp2(d_P0, base+64+c0, w);
        float b1x=p.x*hp.x, b1y=p.y*hp.y;
        #pragma unroll
        for (int i=0;i<3;i++) tY[i] += b1x*ga1[i].x + b1y*ga1[i].y;
        p=lerp2(d_P0, base+128+c0, w);
        float b2x=p.x*hp.x, b2y=p.y*hp.y;
        #pragma unroll
        for (int i=0;i<5;i++) tY[3+i] += b2x*ga2[i].x + b2y*ga2[i].y;
    }
    float x = y[2]*IS3f, yv = y[0]*IS3f, z = y[1]*IS3f;
    float gux = S3f*tY[2] + S15f*(yv*tY[3] + z*tY[6] + x*tY[7]);
    float guy = S3f*tY[0] + S15f*(x*tY[3] + z*tY[4] - yv*tY[7]);
    float guz = S3f*tY[1] + S15f*(yv*tY[4] + x*tY[6]) + 3.f*S5f*z*tY[5];
    gux = warp_sum(gux); guy = warp_sum(guy); guz = warp_sum(guz);
    gr  = warp_sum(gr);
    if (lane==0){
        float inv = 1.0f/r;
        float dot = x*gux + yv*guy + z*guz;
        d_gvec[e*3+0] = (gux - x*dot)*inv + gr*x;
        d_gvec[e*3+1] = (guy - yv*dot)*inv + gr*yv;
        d_gvec[e*3+2] = (guz - z*dot)*inv + gr*z;
    }
}

// ---------------- force gather + finalize (merged) ---------------------------
__global__ void k_force_node(float* __restrict__ out){
    if (blockIdx.x==0 && threadIdx.x<16){
        int g = threadIdx.x;
        float e0=d_e[g], e1=d_e[16+g], e2=d_e[32+g];
        out[g] = e0+e1+e2;
        out[16+g*3+0]=e0; out[16+g*3+1]=e1; out[16+g*3+2]=e2;
    }
    int n = blockIdx.x*4 + (threadIdx.x>>5);
    int lane = threadIdx.x&31;
    float fx=0.f, fy=0.f, fz=0.f;
    int b0=d_off_r[n], b1=d_off_r[n+1];
    for (int q=b0+lane;q<b1;q+=32){
        int e=(int)(((unsigned)__float_as_int(d_erec_r[q*12+3])) & 0x3FFFFu);
        fx-=d_gvec[e*3+0]; fy-=d_gvec[e*3+1]; fz-=d_gvec[e*3+2];
    }
    b0=d_off_s[n]; b1=d_off_s[n+1];
    for (int q=b0+lane;q<b1;q+=32){
        int e=(int)(((unsigned)__float_as_int(d_erec_s[q*12+3])) & 0x3FFFFu);
        fx+=d_gvec[e*3+0]; fy+=d_gvec[e*3+1]; fz+=d_gvec[e*3+2];
    }
    fx=warp_sum(fx); fy=warp_sum(fy); fz=warp_sum(fz);
    if (lane==0){
        float* F = out + 64;
        F[n*3+0]=fx; F[n*3+1]=fy; F[n*3+2]=fz;
    }
}

// ----------------------------------------------------------------------------
extern "C" void kernel_launch(void* const* d_in, const int* in_sizes, int n_in,
                              void* d_out, int out_size){
    const float* pos    = (const float*)d_in[0];
    const float* attrs  = (const float*)d_in[1];
    const float* shifts = (const float*)d_in[2];
    const float* aener  = (const float*)d_in[3];
    const float* w_emb  = (const float*)d_in[4];
    const float* w_up0  = (const float*)d_in[5];
    const float* r0w1   = (const float*)d_in[6];
    const float* r0w2   = (const float*)d_in[7];
    const float* r0w3   = (const float*)d_in[8];
    const float* r0w4   = (const float*)d_in[9];
    const float* w_out0 = (const float*)d_in[10];
    const float* w_sc0  = (const float*)d_in[11];
    const float* w_r0   = (const float*)d_in[12];
    const float* w_up1  = (const float*)d_in[13];
    const float* r1w1   = (const float*)d_in[14];
    const float* r1w2   = (const float*)d_in[15];
    const float* r1w3   = (const float*)d_in[16];
    const float* r1w4   = (const float*)d_in[17];
    const float* w_out1 = (const float*)d_in[18];
    const float* w_sc1  = (const float*)d_in[19];
    const float* w_m1   = (const float*)d_in[20];
    const float* w_m2   = (const float*)d_in[21];
    const int*   ei     = (const int*)d_in[22];
    const int*   batch  = (const int*)d_in[23];
    float* out = (float*)d_out;

    k_prep<<<64,256>>>(attrs, w_out0, w_up1, w_emb, w_up0, w_sc0);
    k_geom_hist<<<625,256>>>(pos, shifts, ei);
    k_scan<<<2,1024>>>(aener, batch);
    k_lut_build<<<dim3(NLUT/8,2),256>>>(r0w1,r0w2,r0w3,r0w4, r1w1,r1w2,r1w3,r1w4);
    k_pair_csr<<<PAIRB+625,256>>>(ei);
    k_int0<<<1184,256>>>(w_out0, w_r0, w_up1, batch);
    k_int1<<<1184,256>>>(w_out1, w_sc1, w_m1, w_m2, w_r0, batch);
    k_int1_bwd<<<1184,256>>>(w_up1, w_out0);
    k_bwd_edge<<<NE*32/256,256>>>();
    k_force_node<<<NN/4,128>>>(out);
}